// round 14
// baseline (speedup 1.0000x reference)
#include <cuda_runtime.h>
#include <cuda_fp16.h>

#define DMODEL 1024
#define NHEADS 16
#define DK     64
#define BATCH  4
#define SEQ    2048
#define ROWS   (BATCH*SEQ)    // 8192
#define BH     (BATCH*NHEADS) // 64

// ---------------- scratch ----------------
__device__ __half   g_xh[(size_t)ROWS*DMODEL];
__device__ unsigned g_whq[(size_t)512*DMODEL];
__device__ unsigned g_whk[(size_t)512*DMODEL];
__device__ unsigned g_whv[(size_t)512*DMODEL];
__device__ unsigned g_who[(size_t)512*DMODEL];
__device__ __half   g_qh[(size_t)BH*SEQ*DK];
__device__ __half   g_kh[(size_t)BH*SEQ*DK];
__device__ __half   g_vh[(size_t)BH*SEQ*DK];
__device__ __half   g_ch[(size_t)ROWS*DMODEL];
__device__ float    g_pre[(size_t)ROWS*DMODEL];
__device__ float    g_rinv[(size_t)BH*SEQ];

// ---------------- helpers ----------------
__device__ __forceinline__ unsigned f2h2(float a, float b) {
    __half2 h = __floats2half2_rn(a, b);
    return *(unsigned*)&h;
}
__device__ __forceinline__ void mma16(float* c, const unsigned* a, const unsigned* b) {
    asm volatile(
        "mma.sync.aligned.m16n8k16.row.col.f32.f16.f16.f32 "
        "{%0,%1,%2,%3}, {%4,%5,%6,%7}, {%8,%9}, {%0,%1,%2,%3};"
        : "+f"(c[0]), "+f"(c[1]), "+f"(c[2]), "+f"(c[3])
        : "r"(a[0]), "r"(a[1]), "r"(a[2]), "r"(a[3]), "r"(b[0]), "r"(b[1]));
}
__device__ __forceinline__ unsigned sptr(const void* p) {
    return (unsigned)__cvta_generic_to_shared(p);
}
__device__ __forceinline__ void ldsm4t(unsigned* r, unsigned a) {
    asm volatile("ldmatrix.sync.aligned.m8n8.x4.trans.shared.b16 {%0,%1,%2,%3}, [%4];"
        : "=r"(r[0]), "=r"(r[1]), "=r"(r[2]), "=r"(r[3]) : "r"(a));
}
__device__ __forceinline__ void cpa16(void* s, const void* g) {
    unsigned ss = (unsigned)__cvta_generic_to_shared(s);
    asm volatile("cp.async.cg.shared.global [%0], [%1], 16;" :: "r"(ss), "l"(g));
}
__device__ __forceinline__ void cpcommit() { asm volatile("cp.async.commit_group;" ::: "memory"); }
__device__ __forceinline__ void cpwait1()  { asm volatile("cp.async.wait_group 1;" ::: "memory"); }
__device__ __forceinline__ void cpwait0()  { asm volatile("cp.async.wait_group 0;" ::: "memory"); }

// ---------------- convert: x -> half, W -> k-pair-interleaved half2 ----------------
__global__ __launch_bounds__(256) void cvt_kernel(
    const float* __restrict__ x,
    const float* __restrict__ Wq, const float* __restrict__ Wk,
    const float* __restrict__ Wv, const float* __restrict__ Wo)
{
    int tid = threadIdx.x;
    if (blockIdx.y == 0) {
        size_t i = ((size_t)blockIdx.x*256 + tid)*8;
        float4 a = *(const float4*)(x + i);
        float4 b = *(const float4*)(x + i + 4);
        uint4 o = make_uint4(f2h2(a.x,a.y), f2h2(a.z,a.w), f2h2(b.x,b.y), f2h2(b.z,b.w));
        *(uint4*)(g_xh + i) = o;
    } else {
        int idx = blockIdx.x*256 + tid;
        if (idx >= 512*256) return;
        const float* W; unsigned* wh;
        if      (blockIdx.y == 1) { W = Wq; wh = g_whq; }
        else if (blockIdx.y == 2) { W = Wk; wh = g_whk; }
        else if (blockIdx.y == 3) { W = Wv; wh = g_whv; }
        else                      { W = Wo; wh = g_who; }
        int kp = idx >> 8, c4 = (idx & 255)*4;
        float4 r0 = *(const float4*)(W + (size_t)(2*kp    )*DMODEL + c4);
        float4 r1 = *(const float4*)(W + (size_t)(2*kp + 1)*DMODEL + c4);
        uint4 o = make_uint4(f2h2(r0.x,r1.x), f2h2(r0.y,r1.y), f2h2(r0.z,r1.z), f2h2(r0.w,r1.w));
        *(uint4*)(wh + (size_t)kp*DMODEL + c4) = o;
    }
}

// ---------------- GEMM: 128x128 tile, k-chunk 64, 3-buffer cp.async ----------------
#define APSTR 36
#define BPSTR 136
#define ABUF (128*APSTR)
#define BBUF (32*BPSTR)
#define GEMM_SMEM (3*(ABUF + BBUF)*4)

__device__ __forceinline__ void gemm5(
    const __half* __restrict__ Ah, const unsigned* __restrict__ Wh,
    const float* __restrict__ bias, const float* __restrict__ resid,
    float* outf, __half* outh, float scale,
    unsigned* sm, int brow, int bcol)
{
    const int tid  = threadIdx.x;
    const int warp = tid >> 5, lane = tid & 31;
    const int g    = lane >> 2, t = lane & 3;
    const int wm   = warp >> 2, wn = warp & 3;

    auto load = [&](int cc) {
        unsigned* Ad = sm + (cc % 3)*(ABUF + BBUF);
        unsigned* Bd = Ad + ABUF;
        int kt = cc * 64;
        #pragma unroll
        for (int j = 0; j < 4; j++) {
            int idx = tid + 256*j;
            int r = idx >> 3, seg = idx & 7;
            cpa16(Ad + r*APSTR + seg*4, Ah + (size_t)(brow + r)*DMODEL + kt + seg*8);
        }
        #pragma unroll
        for (int j = 0; j < 4; j++) {
            int idx = tid + 256*j;
            int kp = idx >> 5, seg = idx & 31;
            cpa16(Bd + kp*BPSTR + seg*4, Wh + (size_t)(kt/2 + kp)*DMODEL + bcol + seg*4);
        }
        cpcommit();
    };

    float c[4][4][4];
    #pragma unroll
    for (int mt = 0; mt < 4; mt++)
        #pragma unroll
        for (int nt = 0; nt < 4; nt++)
            #pragma unroll
            for (int i = 0; i < 4; i++) c[mt][nt][i] = 0.f;

    load(0); load(1);

    for (int cc = 0; cc < 16; cc++) {
        if (cc < 15) cpwait1(); else cpwait0();
        __syncthreads();
        if (cc + 2 < 16) load(cc + 2);
        const unsigned* As = sm + (cc % 3)*(ABUF + BBUF);
        const unsigned* Bs = As + ABUF;

        #pragma unroll
        for (int ks = 0; ks < 4; ks++) {
            int k0 = ks*8;
            unsigned bf[4][2];
            #pragma unroll
            for (int nt = 0; nt < 4; nt++) {
                int col = wn*32 + nt*8 + g;
                bf[nt][0] = Bs[(k0 + t    )*BPSTR + col];
                bf[nt][1] = Bs[(k0 + t + 4)*BPSTR + col];
            }
            #pragma unroll
            for (int mt = 0; mt < 4; mt++) {
                int r0 = wm*64 + mt*16 + g;
                unsigned af[4] = {As[r0*APSTR + k0 + t], As[(r0+8)*APSTR + k0 + t],
                                  As[r0*APSTR + k0 + t + 4], As[(r0+8)*APSTR + k0 + t + 4]};
                #pragma unroll
                for (int nt = 0; nt < 4; nt++) mma16(c[mt][nt], af, bf[nt]);
            }
        }
    }

    #pragma unroll
    for (int mt = 0; mt < 4; mt++)
        #pragma unroll
        for (int nt = 0; nt < 4; nt++)
            #pragma unroll
            for (int half = 0; half < 2; half++) {
                int row = brow + wm*64 + mt*16 + g + half*8;
                int col = bcol + wn*32 + nt*8 + 2*t;
                float v0 = c[mt][nt][half*2 + 0] + bias[col];
                float v1 = c[mt][nt][half*2 + 1] + bias[col + 1];
                if (outh) {
                    v0 *= scale; v1 *= scale;
                    int b = row >> 11, s = row & (SEQ-1);
                    int h = col >> 6,  d = col & (DK-1);
                    *(unsigned*)(outh + (size_t)((b*NHEADS + h)*SEQ + s)*DK + d) = f2h2(v0, v1);
                } else {
                    const float* rp = resid + (size_t)row*DMODEL + col;
                    float2 ov = make_float2(v0 + rp[0], v1 + rp[1]);
                    *(float2*)(outf + (size_t)row*DMODEL + col) = ov;
                }
            }
}

__global__ __launch_bounds__(256, 2) void qkv_tc(
    const float* __restrict__ bq, const float* __restrict__ bk, const float* __restrict__ bv)
{
    extern __shared__ unsigned gsm[];
    const unsigned* Wh; const float* bias; __half* outh; float scale;
    if (blockIdx.z == 0)      { Wh = g_whq; bias = bq; outh = g_qh; scale = 0.125f; }
    else if (blockIdx.z == 1) { Wh = g_whk; bias = bk; outh = g_kh; scale = 1.0f; }
    else                      { Wh = g_whv; bias = bv; outh = g_vh; scale = 1.0f; }
    gemm5(g_xh, Wh, bias, nullptr, nullptr, outh, scale, gsm,
          blockIdx.y * 128, blockIdx.x * 128);
}

__global__ __launch_bounds__(256, 2) void gemmo_tc(
    const float* __restrict__ bo, const float* __restrict__ resid)
{
    extern __shared__ unsigned gsm[];
    gemm5(g_ch, g_who, bo, resid, g_pre, nullptr, 1.0f, gsm,
          blockIdx.y * 128, blockIdx.x * 128);
}

// ---------------- pass A: row sums of exp(QK^T)*mask ----------------
#define QPSTR 36
#define KBUF  (128*QPSTR)
#define SUM_SMEM ((KBUF + 3*KBUF + SEQ + 512)*4)

__global__ __launch_bounds__(256, 2) void attn_sums(
    const int* __restrict__ mask, float* __restrict__ rinvg)
{
    extern __shared__ unsigned sm_[];
    unsigned* Qs   = sm_;
    unsigned* Kb0  = Qs + KBUF;
    float*    mskf = (float*)(Kb0 + 3*KBUF);
    float*    red  = mskf + SEQ;

    const int tid  = threadIdx.x;
    const int warp = tid >> 5, lane = tid & 31;
    const int g    = lane >> 2, t = lane & 3;
    const int wm   = warp >> 2, wn = warp & 3;
    const int q0   = blockIdx.x * 128;
    const int bh   = blockIdx.y;
    const int b    = bh >> 4;
    const __half* Qh = g_qh + (size_t)bh*SEQ*DK;
    const __half* Kh = g_kh + (size_t)bh*SEQ*DK;

    auto loadK = [&](int cc) {
        unsigned* Kd = Kb0 + (cc % 3)*KBUF;
        int kc = cc * 128;
        #pragma unroll
        for (int j = 0; j < 4; j++) {
            int idx = tid + 256*j;
            int r = idx >> 3, seg = idx & 7;
            cpa16(Kd + r*QPSTR + seg*4, Kh + (size_t)(kc + r)*DK + seg*8);
        }
        cpcommit();
    };

    #pragma unroll
    for (int j = 0; j < 4; j++) {
        int idx = tid + 256*j;
        int r = idx >> 3, seg = idx & 7;
        cpa16(Qs + r*QPSTR + seg*4, Qh + (size_t)(q0 + r)*DK + seg*8);
    }
    loadK(0); loadK(1);

    for (int i = tid; i < SEQ; i += 256) mskf[i] = mask[b*SEQ + i] ? 1.f : 0.f;

    float ps[4][2];
    #pragma unroll
    for (int mt = 0; mt < 4; mt++) { ps[mt][0] = 0.f; ps[mt][1] = 0.f; }

    for (int cc = 0; cc < 16; cc++) {
        if (cc < 15) cpwait1(); else cpwait0();
        __syncthreads();
        if (cc + 2 < 16) loadK(cc + 2);
        const unsigned* Ks = Kb0 + (cc % 3)*KBUF;
        int kc = cc * 128;

        float acc[4][4][4];
        #pragma unroll
        for (int mt = 0; mt < 4; mt++)
            #pragma unroll
            for (int nt = 0; nt < 4; nt++)
                #pragma unroll
                for (int i = 0; i < 4; i++) acc[mt][nt][i] = 0.f;

        #pragma unroll
        for (int ks = 0; ks < 4; ks++) {
            int k0 = ks*8;
            unsigned bf[4][2];
            #pragma unroll
            for (int nt = 0; nt < 4; nt++) {
                int col = wn*32 + nt*8 + g;
                bf[nt][0] = Ks[col*QPSTR + k0 + t];
                bf[nt][1] = Ks[col*QPSTR + k0 + t + 4];
            }
            #pragma unroll
            for (int mt = 0; mt < 4; mt++) {
                int r0 = wm*64 + mt*16 + g;
                unsigned af[4] = {Qs[r0*QPSTR + k0 + t], Qs[(r0+8)*QPSTR + k0 + t],
                                  Qs[r0*QPSTR + k0 + t + 4], Qs[(r0+8)*QPSTR + k0 + t + 4]};
                #pragma unroll
                for (int nt = 0; nt < 4; nt++) mma16(acc[mt][nt], af, bf[nt]);
            }
        }
        #pragma unroll
        for (int mt = 0; mt < 4; mt++)
            #pragma unroll
            for (int nt = 0; nt < 4; nt++)
                #pragma unroll
                for (int half = 0; half < 2; half++) {
                    int col = kc + wn*32 + nt*8 + 2*t;
                    ps[mt][half] += __expf(acc[mt][nt][half*2 + 0]) * mskf[col]
                                  + __expf(acc[mt][nt][half*2 + 1]) * mskf[col + 1];
                }
    }

    #pragma unroll
    for (int mt = 0; mt < 4; mt++)
        #pragma unroll
        for (int half = 0; half < 2; half++) {
            float v = ps[mt][half];
            v += __shfl_xor_sync(0xffffffffu, v, 1);
            v += __shfl_xor_sync(0xffffffffu, v, 2);
            if (t == 0) red[wn*128 + wm*64 + mt*16 + g + half*8] = v;
        }
    __syncthreads();
    if (tid < 128) {
        float s = red[tid] + red[128 + tid] + red[256 + tid] + red[384 + tid];
        rinvg[(size_t)bh*SEQ + q0 + tid] = 1.0f / s;
    }
}

// ---------------- pass B: recompute QK, direct att write, register PV ----------------
// Warp grid 8x2: wm=rows (16/warp), wn=key-half (32 keys/warp). No E in smem.
#define FKBUF (64*QPSTR)    // 2304 words
#define RSTR  66
#define FUS_SMEM ((128*QPSTR + 3*FKBUF + 3*FKBUF + SEQ + 128 + 128*RSTR)*4)

__global__ __launch_bounds__(512, 1) void attn_fused(
    const int* __restrict__ mask, const float* __restrict__ rinvg,
    float* __restrict__ attout)
{
    extern __shared__ unsigned sm_[];
    unsigned* Qs   = sm_;                         // [128][QPSTR]
    unsigned* Kb0  = Qs + 128*QPSTR;              // 3 x [64][QPSTR]
    unsigned* Vb0  = Kb0 + 3*FKBUF;               // 3 x [64][QPSTR]
    float*    mskf = (float*)(Vb0 + 3*FKBUF);     // [SEQ]
    float*    rinv = mskf + SEQ;                  // [128]
    float*    red  = rinv + 128;                  // [128][RSTR]
    const unsigned Vbase0 = sptr(Vb0);

    const int tid  = threadIdx.x;
    const int warp = tid >> 5, lane = tid & 31;
    const int g    = lane >> 2, t = lane & 3;
    const int wm   = warp >> 1, wn = warp & 1;     // 8 x 2
    const int q0   = blockIdx.x * 128;
    const int bh   = blockIdx.y;
    const int b    = bh >> 4, h = bh & 15;
    const __half* Qh = g_qh + (size_t)bh*SEQ*DK;
    const __half* Kh = g_kh + (size_t)bh*SEQ*DK;
    const __half* Vh = g_vh + (size_t)bh*SEQ*DK;

    auto loadKV = [&](int cc) {
        unsigned* Kd = Kb0 + (cc % 3)*FKBUF;
        unsigned* Vd = Vb0 + (cc % 3)*FKBUF;
        int kc = cc * 64;
        {
            int r = tid >> 3, seg = tid & 7;
            cpa16(Kd + r*QPSTR + seg*4, Kh + (size_t)(kc + r)*DK + seg*8);
            cpa16(Vd + r*QPSTR + seg*4, Vh + (size_t)(kc + r)*DK + seg*8);
        }
        cpcommit();
    };

    #pragma unroll
    for (int j = 0; j < 2; j++) {
        int idx = tid + 512*j;
        int r = idx >> 3, seg = idx & 7;
        cpa16(Qs + r*QPSTR + seg*4, Qh + (size_t)(q0 + r)*DK + seg*8);
    }
    loadKV(0); loadKV(1);

    for (int i = tid; i < SEQ; i += 512) mskf[i] = mask[b*SEQ + i] ? 1.f : 0.f;
    if (tid < 128) rinv[tid] = rinvg[(size_t)bh*SEQ + q0 + tid];

    float d[8][4];
    #pragma unroll
    for (int nt = 0; nt < 8; nt++)
        #pragma unroll
        for (int i = 0; i < 4; i++) d[nt][i] = 0.f;

    const int r0 = wm*16 + g;         // this thread's base row (and r0+8)
    float* attrow0 = attout + ((size_t)bh*SEQ + q0 + r0)*SEQ;
    float* attrow1 = attout + ((size_t)bh*SEQ + q0 + r0 + 8)*SEQ;
    const float iv0 = rinvg[(size_t)bh*SEQ + q0 + r0];
    const float iv1 = rinvg[(size_t)bh*SEQ + q0 + r0 + 8];

    for (int cc = 0; cc < 32; cc++) {
        if (cc < 31) cpwait1(); else cpwait0();
        __syncthreads();
        if (cc + 2 < 32) loadKV(cc + 2);
        const unsigned* Kp = Kb0 + (cc % 3)*FKBUF;
        const unsigned  Vbase = Vbase0 + (unsigned)((cc % 3)*FKBUF)*4;
        int kc = cc * 64;

        // ---- QK: 16 rows x 32 keys (same d-chain order as attn_sums) ----
        float s[4][4];
        #pragma unroll
        for (int nt = 0; nt < 4; nt++)
            #pragma unroll
            for (int i = 0; i < 4; i++) s[nt][i] = 0.f;

        #pragma unroll
        for (int ks = 0; ks < 4; ks++) {
            int k0 = ks*8;
            unsigned af[4] = {Qs[r0*QPSTR + k0 + t], Qs[(r0+8)*QPSTR + k0 + t],
                              Qs[r0*QPSTR + k0 + t + 4], Qs[(r0+8)*QPSTR + k0 + t + 4]};
            #pragma unroll
            for (int nt = 0; nt < 4; nt++) {
                int col = wn*32 + nt*8 + g;
                unsigned bf[2] = {Kp[col*QPSTR + k0 + t], Kp[col*QPSTR + k0 + t + 4]};
                mma16(s[nt], af, bf);
            }
        }

        // ---- epilogue: e in registers, att written directly ----
        float e[4][4];
        #pragma unroll
        for (int nt = 0; nt < 4; nt++) {
            int col = wn*32 + nt*8 + 2*t;
            float m0 = mskf[kc + col], m1 = mskf[kc + col + 1];
            e[nt][0] = __expf(s[nt][0]) * m0 * iv0;
            e[nt][1] = __expf(s[nt][1]) * m1 * iv0;
            e[nt][2] = __expf(s[nt][2]) * m0 * iv1;
            e[nt][3] = __expf(s[nt][3]) * m1 * iv1;
            *(float2*)(attrow0 + kc + col) = make_float2(e[nt][0], e[nt][1]);
            *(float2*)(attrow1 + kc + col) = make_float2(e[nt][2], e[nt][3]);
        }

        // ---- PV: A-fragments straight from registers; V via ldmatrix.trans ----
        #pragma unroll
        for (int ks2 = 0; ks2 < 2; ks2++) {
            unsigned af[4] = {f2h2(e[ks2*2][0],   e[ks2*2][1]),
                              f2h2(e[ks2*2][2],   e[ks2*2][3]),
                              f2h2(e[ks2*2+1][0], e[ks2*2+1][1]),
                              f2h2(e[ks2*2+1][2], e[ks2*2+1][3])};
            #pragma unroll
            for (int nt2 = 0; nt2 < 4; nt2++) {
                unsigned rr[4];
                unsigned a = Vbase
                    + (unsigned)((wn*32 + ks2*16 + (lane & 15))*QPSTR)*4
                    + (unsigned)(nt2*16)*2 + (lane >> 4)*16;
                ldsm4t(rr, a);
                mma16(d[nt2*2    ], af, rr);
                mma16(d[nt2*2 + 1], af, rr + 2);
            }
        }
    }

    // ---- cross-warp key-half reduction (once) + ctx write ----
    __syncthreads();
    if (wn == 1) {
        #pragma unroll
        for (int nt = 0; nt < 8; nt++)
            #pragma unroll
            for (int half = 0; half < 2; half++) {
                int row = wm*16 + g + half*8;
                int col = nt*8 + 2*t;
                *(float2*)(red + row*RSTR + col) =
                    make_float2(d[nt][half*2 + 0], d[nt][half*2 + 1]);
            }
    }
    __syncthreads();
    if (wn == 0) {
        #pragma unroll
        for (int nt = 0; nt < 8; nt++)
            #pragma unroll
            for (int half = 0; half < 2; half++) {
                int row = wm*16 + g + half*8;
                int col = nt*8 + 2*t;
                float2 o = *(const float2*)(red + row*RSTR + col);
                float v0 = d[nt][half*2 + 0] + o.x;
                float v1 = d[nt][half*2 + 1] + o.y;
                *(unsigned*)(g_ch + (size_t)(b*SEQ + q0 + row)*DMODEL + h*DK + col) = f2h2(v0, v1);
            }
    }
}

// ---------------- LayerNorm ----------------
__global__ __launch_bounds__(256) void ln_kernel(
    const float* __restrict__ pre, const float* __restrict__ gamma,
    const float* __restrict__ beta, float* __restrict__ out)
{
    const int tid = threadIdx.x;
    const int row = blockIdx.x;
    float4 v = ((const float4*)(pre + (size_t)row*DMODEL))[tid];
    float s  = v.x + v.y + v.z + v.w;
    float s2 = v.x*v.x + v.y*v.y + v.z*v.z + v.w*v.w;
    #pragma unroll
    for (int o = 16; o > 0; o >>= 1) {
        s  += __shfl_xor_sync(0xffffffffu, s,  o);
        s2 += __shfl_xor_sync(0xffffffffu, s2, o);
    }
    __shared__ float ws[8], ws2[8];
    __shared__ float mu_s, r_s;
    if ((tid & 31) == 0) { ws[tid >> 5] = s; ws2[tid >> 5] = s2; }
    __syncthreads();
    if (tid == 0) {
        float tt = 0.f, t2 = 0.f;
        #pragma unroll
        for (int i = 0; i < 8; i++) { tt += ws[i]; t2 += ws2[i]; }
        float mu  = tt * (1.0f/DMODEL);
        float var = t2 * (1.0f/DMODEL) - mu*mu;
        mu_s = mu;
        r_s  = rsqrtf(var + 1e-5f);
    }
    __syncthreads();
    float mu = mu_s, r = r_s;
    float4 gm = ((const float4*)gamma)[tid];
    float4 be = ((const float4*)beta)[tid];
    float4 o;
    o.x = (v.x - mu)*r*gm.x + be.x;
    o.y = (v.y - mu)*r*gm.y + be.y;
    o.z = (v.z - mu)*r*gm.z + be.z;
    o.w = (v.w - mu)*r*gm.w + be.w;
    ((float4*)(out + (size_t)row*DMODEL))[tid] = o;
}

// ---------------- launch ----------------
extern "C" void kernel_launch(void* const* d_in, const int* in_sizes, int n_in,
                              void* d_out, int out_size)
{
    const float* x     = (const float*)d_in[0];
    const int*   mask  = (const int*)  d_in[1];
    const float* Wq    = (const float*)d_in[2];
    const float* bq    = (const float*)d_in[3];
    const float* Wk    = (const float*)d_in[4];
    const float* bk    = (const float*)d_in[5];
    const float* Wv    = (const float*)d_in[6];
    const float* bv    = (const float*)d_in[7];
    const float* Wo    = (const float*)d_in[8];
    const float* bo    = (const float*)d_in[9];
    const float* gamma = (const float*)d_in[10];
    const float* beta  = (const float*)d_in[11];
    float* out = (float*)d_out;

    void *ppre, *pri;
    cudaGetSymbolAddress(&ppre, g_pre);
    cudaGetSymbolAddress(&pri,  g_rinv);

    const long long OUT_ELEMS = (long long)ROWS * DMODEL;
    float* attout = out + OUT_ELEMS;

    cudaFuncSetAttribute(qkv_tc,     cudaFuncAttributeMaxDynamicSharedMemorySize, GEMM_SMEM);
    cudaFuncSetAttribute(gemmo_tc,   cudaFuncAttributeMaxDynamicSharedMemorySize, GEMM_SMEM);
    cudaFuncSetAttribute(attn_sums,  cudaFuncAttributeMaxDynamicSharedMemorySize, SUM_SMEM);
    cudaFuncSetAttribute(attn_fused, cudaFuncAttributeMaxDynamicSharedMemorySize, FUS_SMEM);

    cvt_kernel<<<dim3(4096, 5), 256>>>(x, Wq, Wk, Wv, Wo);

    qkv_tc<<<dim3(DMODEL/128, ROWS/128, 3), 256, GEMM_SMEM>>>(bq, bk, bv);

    attn_sums<<<dim3(SEQ/128, BH), 256, SUM_SMEM>>>(mask, (float*)pri);
    attn_fused<<<dim3(SEQ/128, BH), 512, FUS_SMEM>>>(mask, (const float*)pri, attout);

    gemmo_tc<<<dim3(DMODEL/128, ROWS/128), 256, GEMM_SMEM>>>(bo, x);
    ln_kernel<<<ROWS, 256>>>((const float*)ppre, gamma, beta, out);
}

// round 15
// speedup vs baseline: 1.0308x; 1.0308x over previous
#include <cuda_runtime.h>
#include <cuda_fp16.h>

#define DMODEL 1024
#define NHEADS 16
#define DK     64
#define BATCH  4
#define SEQ    2048
#define ROWS   (BATCH*SEQ)    // 8192
#define BH     (BATCH*NHEADS) // 64

// ---------------- scratch ----------------
__device__ __half   g_xh[(size_t)ROWS*DMODEL];
__device__ unsigned g_whq[(size_t)512*DMODEL];
__device__ unsigned g_whk[(size_t)512*DMODEL];
__device__ unsigned g_whv[(size_t)512*DMODEL];
__device__ unsigned g_who[(size_t)512*DMODEL];
__device__ __half   g_qh[(size_t)BH*SEQ*DK];
__device__ __half   g_kh[(size_t)BH*SEQ*DK];
__device__ __half   g_vh[(size_t)BH*SEQ*DK];
__device__ __half   g_ch[(size_t)ROWS*DMODEL];
__device__ float    g_pre[(size_t)ROWS*DMODEL];
__device__ float    g_rinv[(size_t)BH*SEQ];

// ---------------- helpers ----------------
__device__ __forceinline__ unsigned f2h2(float a, float b) {
    __half2 h = __floats2half2_rn(a, b);
    return *(unsigned*)&h;
}
__device__ __forceinline__ void mma16(float* c, const unsigned* a, const unsigned* b) {
    asm volatile(
        "mma.sync.aligned.m16n8k16.row.col.f32.f16.f16.f32 "
        "{%0,%1,%2,%3}, {%4,%5,%6,%7}, {%8,%9}, {%0,%1,%2,%3};"
        : "+f"(c[0]), "+f"(c[1]), "+f"(c[2]), "+f"(c[3])
        : "r"(a[0]), "r"(a[1]), "r"(a[2]), "r"(a[3]), "r"(b[0]), "r"(b[1]));
}
__device__ __forceinline__ unsigned sptr(const void* p) {
    return (unsigned)__cvta_generic_to_shared(p);
}
__device__ __forceinline__ void ldsm4(unsigned* r, unsigned a) {
    asm volatile("ldmatrix.sync.aligned.m8n8.x4.shared.b16 {%0,%1,%2,%3}, [%4];"
        : "=r"(r[0]), "=r"(r[1]), "=r"(r[2]), "=r"(r[3]) : "r"(a));
}
__device__ __forceinline__ void ldsm4t(unsigned* r, unsigned a) {
    asm volatile("ldmatrix.sync.aligned.m8n8.x4.trans.shared.b16 {%0,%1,%2,%3}, [%4];"
        : "=r"(r[0]), "=r"(r[1]), "=r"(r[2]), "=r"(r[3]) : "r"(a));
}
__device__ __forceinline__ void cpa16(void* s, const void* g) {
    unsigned ss = (unsigned)__cvta_generic_to_shared(s);
    asm volatile("cp.async.cg.shared.global [%0], [%1], 16;" :: "r"(ss), "l"(g));
}
__device__ __forceinline__ void cpcommit() { asm volatile("cp.async.commit_group;" ::: "memory"); }
__device__ __forceinline__ void cpwait1()  { asm volatile("cp.async.wait_group 1;" ::: "memory"); }
__device__ __forceinline__ void cpwait0()  { asm volatile("cp.async.wait_group 0;" ::: "memory"); }

// ---------------- convert: x -> half, W -> k-pair-interleaved half2 ----------------
__global__ __launch_bounds__(256) void cvt_kernel(
    const float* __restrict__ x,
    const float* __restrict__ Wq, const float* __restrict__ Wk,
    const float* __restrict__ Wv, const float* __restrict__ Wo)
{
    int tid = threadIdx.x;
    if (blockIdx.y == 0) {
        size_t i = ((size_t)blockIdx.x*256 + tid)*8;
        float4 a = *(const float4*)(x + i);
        float4 b = *(const float4*)(x + i + 4);
        uint4 o = make_uint4(f2h2(a.x,a.y), f2h2(a.z,a.w), f2h2(b.x,b.y), f2h2(b.z,b.w));
        *(uint4*)(g_xh + i) = o;
    } else {
        int idx = blockIdx.x*256 + tid;
        if (idx >= 512*256) return;
        const float* W; unsigned* wh;
        if      (blockIdx.y == 1) { W = Wq; wh = g_whq; }
        else if (blockIdx.y == 2) { W = Wk; wh = g_whk; }
        else if (blockIdx.y == 3) { W = Wv; wh = g_whv; }
        else                      { W = Wo; wh = g_who; }
        int kp = idx >> 8, c4 = (idx & 255)*4;
        float4 r0 = *(const float4*)(W + (size_t)(2*kp    )*DMODEL + c4);
        float4 r1 = *(const float4*)(W + (size_t)(2*kp + 1)*DMODEL + c4);
        uint4 o = make_uint4(f2h2(r0.x,r1.x), f2h2(r0.y,r1.y), f2h2(r0.z,r1.z), f2h2(r0.w,r1.w));
        *(uint4*)(wh + (size_t)kp*DMODEL + c4) = o;
    }
}

// ---------------- GEMM: 128x128 tile, k-chunk 64, 3-buffer cp.async ----------------
#define APSTR 36
#define BPSTR 136
#define ABUF (128*APSTR)
#define BBUF (32*BPSTR)
#define GEMM_SMEM (3*(ABUF + BBUF)*4)

__device__ __forceinline__ void gemm5(
    const __half* __restrict__ Ah, const unsigned* __restrict__ Wh,
    const float* __restrict__ bias, const float* __restrict__ resid,
    float* outf, __half* outh, float scale,
    unsigned* sm, int brow, int bcol)
{
    const int tid  = threadIdx.x;
    const int warp = tid >> 5, lane = tid & 31;
    const int g    = lane >> 2, t = lane & 3;
    const int wm   = warp >> 2, wn = warp & 3;

    auto load = [&](int cc) {
        unsigned* Ad = sm + (cc % 3)*(ABUF + BBUF);
        unsigned* Bd = Ad + ABUF;
        int kt = cc * 64;
        #pragma unroll
        for (int j = 0; j < 4; j++) {
            int idx = tid + 256*j;
            int r = idx >> 3, seg = idx & 7;
            cpa16(Ad + r*APSTR + seg*4, Ah + (size_t)(brow + r)*DMODEL + kt + seg*8);
        }
        #pragma unroll
        for (int j = 0; j < 4; j++) {
            int idx = tid + 256*j;
            int kp = idx >> 5, seg = idx & 31;
            cpa16(Bd + kp*BPSTR + seg*4, Wh + (size_t)(kt/2 + kp)*DMODEL + bcol + seg*4);
        }
        cpcommit();
    };

    float c[4][4][4];
    #pragma unroll
    for (int mt = 0; mt < 4; mt++)
        #pragma unroll
        for (int nt = 0; nt < 4; nt++)
            #pragma unroll
            for (int i = 0; i < 4; i++) c[mt][nt][i] = 0.f;

    load(0); load(1);

    for (int cc = 0; cc < 16; cc++) {
        if (cc < 15) cpwait1(); else cpwait0();
        __syncthreads();
        if (cc + 2 < 16) load(cc + 2);
        const unsigned* As = sm + (cc % 3)*(ABUF + BBUF);
        const unsigned* Bs = As + ABUF;

        #pragma unroll
        for (int ks = 0; ks < 4; ks++) {
            int k0 = ks*8;
            unsigned bf[4][2];
            #pragma unroll
            for (int nt = 0; nt < 4; nt++) {
                int col = wn*32 + nt*8 + g;
                bf[nt][0] = Bs[(k0 + t    )*BPSTR + col];
                bf[nt][1] = Bs[(k0 + t + 4)*BPSTR + col];
            }
            #pragma unroll
            for (int mt = 0; mt < 4; mt++) {
                int r0 = wm*64 + mt*16 + g;
                unsigned af[4] = {As[r0*APSTR + k0 + t], As[(r0+8)*APSTR + k0 + t],
                                  As[r0*APSTR + k0 + t + 4], As[(r0+8)*APSTR + k0 + t + 4]};
                #pragma unroll
                for (int nt = 0; nt < 4; nt++) mma16(c[mt][nt], af, bf[nt]);
            }
        }
    }

    #pragma unroll
    for (int mt = 0; mt < 4; mt++)
        #pragma unroll
        for (int nt = 0; nt < 4; nt++)
            #pragma unroll
            for (int half = 0; half < 2; half++) {
                int row = brow + wm*64 + mt*16 + g + half*8;
                int col = bcol + wn*32 + nt*8 + 2*t;
                float v0 = c[mt][nt][half*2 + 0] + bias[col];
                float v1 = c[mt][nt][half*2 + 1] + bias[col + 1];
                if (outh) {
                    v0 *= scale; v1 *= scale;
                    int b = row >> 11, s = row & (SEQ-1);
                    int h = col >> 6,  d = col & (DK-1);
                    *(unsigned*)(outh + (size_t)((b*NHEADS + h)*SEQ + s)*DK + d) = f2h2(v0, v1);
                } else {
                    const float* rp = resid + (size_t)row*DMODEL + col;
                    float2 ov = make_float2(v0 + rp[0], v1 + rp[1]);
                    *(float2*)(outf + (size_t)row*DMODEL + col) = ov;
                }
            }
}

__global__ __launch_bounds__(256, 2) void qkv_tc(
    const float* __restrict__ bq, const float* __restrict__ bk, const float* __restrict__ bv)
{
    extern __shared__ unsigned gsm[];
    const unsigned* Wh; const float* bias; __half* outh; float scale;
    if (blockIdx.z == 0)      { Wh = g_whq; bias = bq; outh = g_qh; scale = 0.125f; }
    else if (blockIdx.z == 1) { Wh = g_whk; bias = bk; outh = g_kh; scale = 1.0f; }
    else                      { Wh = g_whv; bias = bv; outh = g_vh; scale = 1.0f; }
    gemm5(g_xh, Wh, bias, nullptr, nullptr, outh, scale, gsm,
          blockIdx.y * 128, blockIdx.x * 128);
}

__global__ __launch_bounds__(256, 2) void gemmo_tc(
    const float* __restrict__ bo, const float* __restrict__ resid)
{
    extern __shared__ unsigned gsm[];
    gemm5(g_ch, g_who, bo, resid, g_pre, nullptr, 1.0f, gsm,
          blockIdx.y * 128, blockIdx.x * 128);
}

// ---------------- pass A: row sums of exp(QK^T)*mask ----------------
#define QPSTR 36
#define KBUF  (128*QPSTR)
#define SUM_SMEM ((KBUF + 3*KBUF + SEQ + 512)*4)

__global__ __launch_bounds__(256, 2) void attn_sums(
    const int* __restrict__ mask, float* __restrict__ rinvg)
{
    extern __shared__ unsigned sm_[];
    unsigned* Qs   = sm_;
    unsigned* Kb0  = Qs + KBUF;
    float*    mskf = (float*)(Kb0 + 3*KBUF);
    float*    red  = mskf + SEQ;
    const unsigned Qbase  = sptr(Qs);
    const unsigned Kbase0 = sptr(Kb0);

    const int tid  = threadIdx.x;
    const int warp = tid >> 5, lane = tid & 31;
    const int g    = lane >> 2, t = lane & 3;
    const int wm   = warp >> 2, wn = warp & 3;
    const int q0   = blockIdx.x * 128;
    const int bh   = blockIdx.y;
    const int b    = bh >> 4;
    const __half* Qh = g_qh + (size_t)bh*SEQ*DK;
    const __half* Kh = g_kh + (size_t)bh*SEQ*DK;

    auto loadK = [&](int cc) {
        unsigned* Kd = Kb0 + (cc % 3)*KBUF;
        int kc = cc * 128;
        #pragma unroll
        for (int j = 0; j < 4; j++) {
            int idx = tid + 256*j;
            int r = idx >> 3, seg = idx & 7;
            cpa16(Kd + r*QPSTR + seg*4, Kh + (size_t)(kc + r)*DK + seg*8);
        }
        cpcommit();
    };

    #pragma unroll
    for (int j = 0; j < 4; j++) {
        int idx = tid + 256*j;
        int r = idx >> 3, seg = idx & 7;
        cpa16(Qs + r*QPSTR + seg*4, Qh + (size_t)(q0 + r)*DK + seg*8);
    }
    loadK(0); loadK(1);

    for (int i = tid; i < SEQ; i += 256) mskf[i] = mask[b*SEQ + i] ? 1.f : 0.f;

    float ps[4][2];
    #pragma unroll
    for (int mt = 0; mt < 4; mt++) { ps[mt][0] = 0.f; ps[mt][1] = 0.f; }

    for (int cc = 0; cc < 16; cc++) {
        if (cc < 15) cpwait1(); else cpwait0();
        __syncthreads();
        if (cc + 2 < 16) loadK(cc + 2);
        const unsigned Kbase = Kbase0 + (unsigned)((cc % 3)*KBUF)*4;
        int kc = cc * 128;

        float acc[4][4][4];
        #pragma unroll
        for (int mt = 0; mt < 4; mt++)
            #pragma unroll
            for (int nt = 0; nt < 4; nt++)
                #pragma unroll
                for (int i = 0; i < 4; i++) acc[mt][nt][i] = 0.f;

        #pragma unroll
        for (int ks = 0; ks < 4; ks++) {
            unsigned bf[4][2];
            #pragma unroll
            for (int ntp = 0; ntp < 2; ntp++) {
                unsigned rr[4];
                int key = wn*32 + ntp*16 + (lane & 7) + ((lane & 16) ? 8 : 0);
                unsigned a = Kbase + (unsigned)(key*QPSTR + ks*8)*4 + ((lane >> 3) & 1)*16;
                ldsm4(rr, a);
                bf[2*ntp][0] = rr[0]; bf[2*ntp][1] = rr[1];
                bf[2*ntp+1][0] = rr[2]; bf[2*ntp+1][1] = rr[3];
            }
            #pragma unroll
            for (int mt = 0; mt < 4; mt++) {
                unsigned af[4];
                unsigned a = Qbase + (unsigned)((wm*64 + mt*16 + (lane & 15))*QPSTR + ks*8)*4
                           + (lane >> 4)*16;
                ldsm4(af, a);
                #pragma unroll
                for (int nt = 0; nt < 4; nt++) mma16(acc[mt][nt], af, bf[nt]);
            }
        }
        #pragma unroll
        for (int mt = 0; mt < 4; mt++)
            #pragma unroll
            for (int nt = 0; nt < 4; nt++)
                #pragma unroll
                for (int half = 0; half < 2; half++) {
                    int col = kc + wn*32 + nt*8 + 2*t;
                    ps[mt][half] += __expf(acc[mt][nt][half*2 + 0]) * mskf[col]
                                  + __expf(acc[mt][nt][half*2 + 1]) * mskf[col + 1];
                }
    }

    #pragma unroll
    for (int mt = 0; mt < 4; mt++)
        #pragma unroll
        for (int half = 0; half < 2; half++) {
            float v = ps[mt][half];
            v += __shfl_xor_sync(0xffffffffu, v, 1);
            v += __shfl_xor_sync(0xffffffffu, v, 2);
            if (t == 0) red[wn*128 + wm*64 + mt*16 + g + half*8] = v;
        }
    __syncthreads();
    if (tid < 128) {
        float s = red[tid] + red[128 + tid] + red[256 + tid] + red[384 + tid];
        rinvg[(size_t)bh*SEQ + q0 + tid] = 1.0f / s;
    }
}

// ---------------- pass B: recompute QK, direct att write, register PV ----------------
#define FKBUF (64*QPSTR)
#define RSTR  66
#define FUS_SMEM ((128*QPSTR + 3*FKBUF + 3*FKBUF + SEQ + 128 + 128*RSTR)*4)

__global__ __launch_bounds__(512, 1) void attn_fused(
    const int* __restrict__ mask, const float* __restrict__ rinvg,
    float* __restrict__ attout)
{
    extern __shared__ unsigned sm_[];
    unsigned* Qs   = sm_;                         // [128][QPSTR]
    unsigned* Kb0  = Qs + 128*QPSTR;              // 3 x [64][QPSTR]
    unsigned* Vb0  = Kb0 + 3*FKBUF;               // 3 x [64][QPSTR]
    float*    mskf = (float*)(Vb0 + 3*FKBUF);     // [SEQ]
    float*    rinv = mskf + SEQ;                  // [128]
    float*    red  = rinv + 128;                  // [128][RSTR]
    const unsigned Qbase  = sptr(Qs);
    const unsigned Kbase0 = sptr(Kb0);
    const unsigned Vbase0 = sptr(Vb0);

    const int tid  = threadIdx.x;
    const int warp = tid >> 5, lane = tid & 31;
    const int g    = lane >> 2, t = lane & 3;
    const int wm   = warp >> 1, wn = warp & 1;     // 8 x 2
    const int q0   = blockIdx.x * 128;
    const int bh   = blockIdx.y;
    const int b    = bh >> 4, h = bh & 15;
    const __half* Qh = g_qh + (size_t)bh*SEQ*DK;
    const __half* Kh = g_kh + (size_t)bh*SEQ*DK;
    const __half* Vh = g_vh + (size_t)bh*SEQ*DK;

    auto loadKV = [&](int cc) {
        unsigned* Kd = Kb0 + (cc % 3)*FKBUF;
        unsigned* Vd = Vb0 + (cc % 3)*FKBUF;
        int kc = cc * 64;
        {
            int r = tid >> 3, seg = tid & 7;
            cpa16(Kd + r*QPSTR + seg*4, Kh + (size_t)(kc + r)*DK + seg*8);
            cpa16(Vd + r*QPSTR + seg*4, Vh + (size_t)(kc + r)*DK + seg*8);
        }
        cpcommit();
    };

    #pragma unroll
    for (int j = 0; j < 2; j++) {
        int idx = tid + 512*j;
        int r = idx >> 3, seg = idx & 7;
        cpa16(Qs + r*QPSTR + seg*4, Qh + (size_t)(q0 + r)*DK + seg*8);
    }
    loadKV(0); loadKV(1);

    for (int i = tid; i < SEQ; i += 512) mskf[i] = mask[b*SEQ + i] ? 1.f : 0.f;
    if (tid < 128) rinv[tid] = rinvg[(size_t)bh*SEQ + q0 + tid];

    float d[8][4];
    #pragma unroll
    for (int nt = 0; nt < 8; nt++)
        #pragma unroll
        for (int i = 0; i < 4; i++) d[nt][i] = 0.f;

    const int r0 = wm*16 + g;
    float* attrow0 = attout + ((size_t)bh*SEQ + q0 + r0)*SEQ;
    float* attrow1 = attout + ((size_t)bh*SEQ + q0 + r0 + 8)*SEQ;
    const float iv0 = rinvg[(size_t)bh*SEQ + q0 + r0];
    const float iv1 = rinvg[(size_t)bh*SEQ + q0 + r0 + 8];

    for (int cc = 0; cc < 32; cc++) {
        if (cc < 31) cpwait1(); else cpwait0();
        __syncthreads();
        if (cc + 2 < 32) loadKV(cc + 2);
        const unsigned Kbase = Kbase0 + (unsigned)((cc % 3)*FKBUF)*4;
        const unsigned Vbase = Vbase0 + (unsigned)((cc % 3)*FKBUF)*4;
        int kc = cc * 64;

        // ---- QK: 16 rows x 32 keys, fragments via ldmatrix ----
        float s[4][4];
        #pragma unroll
        for (int nt = 0; nt < 4; nt++)
            #pragma unroll
            for (int i = 0; i < 4; i++) s[nt][i] = 0.f;

        #pragma unroll
        for (int ks = 0; ks < 4; ks++) {
            unsigned af[4];
            {
                unsigned a = Qbase + (unsigned)((wm*16 + (lane & 15))*QPSTR + ks*8)*4
                           + (lane >> 4)*16;
                ldsm4(af, a);
            }
            unsigned bf[4][2];
            #pragma unroll
            for (int ntp = 0; ntp < 2; ntp++) {
                unsigned rr[4];
                int key = wn*32 + ntp*16 + (lane & 7) + ((lane & 16) ? 8 : 0);
                unsigned a = Kbase + (unsigned)(key*QPSTR + ks*8)*4 + ((lane >> 3) & 1)*16;
                ldsm4(rr, a);
                bf[2*ntp][0] = rr[0]; bf[2*ntp][1] = rr[1];
                bf[2*ntp+1][0] = rr[2]; bf[2*ntp+1][1] = rr[3];
            }
            #pragma unroll
            for (int nt = 0; nt < 4; nt++) mma16(s[nt], af, bf[nt]);
        }

        // ---- epilogue: e in registers, att written directly ----
        float e[4][4];
        #pragma unroll
        for (int nt = 0; nt < 4; nt++) {
            int col = wn*32 + nt*8 + 2*t;
            float m0 = mskf[kc + col], m1 = mskf[kc + col + 1];
            e[nt][0] = __expf(s[nt][0]) * m0 * iv0;
            e[nt][1] = __expf(s[nt][1]) * m1 * iv0;
            e[nt][2] = __expf(s[nt][2]) * m0 * iv1;
            e[nt][3] = __expf(s[nt][3]) * m1 * iv1;
            *(float2*)(attrow0 + kc + col) = make_float2(e[nt][0], e[nt][1]);
            *(float2*)(attrow1 + kc + col) = make_float2(e[nt][2], e[nt][3]);
        }

        // ---- PV: A-fragments from registers; V via ldmatrix.trans ----
        #pragma unroll
        for (int ks2 = 0; ks2 < 2; ks2++) {
            unsigned af[4] = {f2h2(e[ks2*2][0],   e[ks2*2][1]),
                              f2h2(e[ks2*2][2],   e[ks2*2][3]),
                              f2h2(e[ks2*2+1][0], e[ks2*2+1][1]),
                              f2h2(e[ks2*2+1][2], e[ks2*2+1][3])};
            #pragma unroll
            for (int nt2 = 0; nt2 < 4; nt2++) {
                unsigned rr[4];
                unsigned a = Vbase
                    + (unsigned)((wn*32 + ks2*16 + (lane & 15))*QPSTR)*4
                    + (unsigned)(nt2*16)*2 + (lane >> 4)*16;
                ldsm4t(rr, a);
                mma16(d[nt2*2    ], af, rr);
                mma16(d[nt2*2 + 1], af, rr + 2);
            }
        }
    }

    // ---- cross-warp key-half reduction + ctx write ----
    __syncthreads();
    if (wn == 1) {
        #pragma unroll
        for (int nt = 0; nt < 8; nt++)
            #pragma unroll
            for (int half = 0; half < 2; half++) {
                int row = wm*16 + g + half*8;
                int col = nt*8 + 2*t;
                *(float2*)(red + row*RSTR + col) =
                    make_float2(d[nt][half*2 + 0], d[nt][half*2 + 1]);
            }
    }
    __syncthreads();
    if (wn == 0) {
        #pragma unroll
        for (int nt = 0; nt < 8; nt++)
            #pragma unroll
            for (int half = 0; half < 2; half++) {
                int row = wm*16 + g + half*8;
                int col = nt*8 + 2*t;
                float2 o = *(const float2*)(red + row*RSTR + col);
                float v0 = d[nt][half*2 + 0] + o.x;
                float v1 = d[nt][half*2 + 1] + o.y;
                *(unsigned*)(g_ch + (size_t)(b*SEQ + q0 + row)*DMODEL + h*DK + col) = f2h2(v0, v1);
            }
    }
}

// ---------------- LayerNorm ----------------
__global__ __launch_bounds__(256) void ln_kernel(
    const float* __restrict__ pre, const float* __restrict__ gamma,
    const float* __restrict__ beta, float* __restrict__ out)
{
    const int tid = threadIdx.x;
    const int row = blockIdx.x;
    float4 v = ((const float4*)(pre + (size_t)row*DMODEL))[tid];
    float s  = v.x + v.y + v.z + v.w;
    float s2 = v.x*v.x + v.y*v.y + v.z*v.z + v.w*v.w;
    #pragma unroll
    for (int o = 16; o > 0; o >>= 1) {
        s  += __shfl_xor_sync(0xffffffffu, s,  o);
        s2 += __shfl_xor_sync(0xffffffffu, s2, o);
    }
    __shared__ float ws[8], ws2[8];
    __shared__ float mu_s, r_s;
    if ((tid & 31) == 0) { ws[tid >> 5] = s; ws2[tid >> 5] = s2; }
    __syncthreads();
    if (tid == 0) {
        float tt = 0.f, t2 = 0.f;
        #pragma unroll
        for (int i = 0; i < 8; i++) { tt += ws[i]; t2 += ws2[i]; }
        float mu  = tt * (1.0f/DMODEL);
        float var = t2 * (1.0f/DMODEL) - mu*mu;
        mu_s = mu;
        r_s  = rsqrtf(var + 1e-5f);
    }
    __syncthreads();
    float mu = mu_s, r = r_s;
    float4 gm = ((const float4*)gamma)[tid];
    float4 be = ((const float4*)beta)[tid];
    float4 o;
    o.x = (v.x - mu)*r*gm.x + be.x;
    o.y = (v.y - mu)*r*gm.y + be.y;
    o.z = (v.z - mu)*r*gm.z + be.z;
    o.w = (v.w - mu)*r*gm.w + be.w;
    ((float4*)(out + (size_t)row*DMODEL))[tid] = o;
}

// ---------------- launch ----------------
extern "C" void kernel_launch(void* const* d_in, const int* in_sizes, int n_in,
                              void* d_out, int out_size)
{
    const float* x     = (const float*)d_in[0];
    const int*   mask  = (const int*)  d_in[1];
    const float* Wq    = (const float*)d_in[2];
    const float* bq    = (const float*)d_in[3];
    const float* Wk    = (const float*)d_in[4];
    const float* bk    = (const float*)d_in[5];
    const float* Wv    = (const float*)d_in[6];
    const float* bv    = (const float*)d_in[7];
    const float* Wo    = (const float*)d_in[8];
    const float* bo    = (const float*)d_in[9];
    const float* gamma = (const float*)d_in[10];
    const float* beta  = (const float*)d_in[11];
    float* out = (float*)d_out;

    void *ppre, *pri;
    cudaGetSymbolAddress(&ppre, g_pre);
    cudaGetSymbolAddress(&pri,  g_rinv);

    const long long OUT_ELEMS = (long long)ROWS * DMODEL;
    float* attout = out + OUT_ELEMS;

    cudaFuncSetAttribute(qkv_tc,     cudaFuncAttributeMaxDynamicSharedMemorySize, GEMM_SMEM);
    cudaFuncSetAttribute(gemmo_tc,   cudaFuncAttributeMaxDynamicSharedMemorySize, GEMM_SMEM);
    cudaFuncSetAttribute(attn_sums,  cudaFuncAttributeMaxDynamicSharedMemorySize, SUM_SMEM);
    cudaFuncSetAttribute(attn_fused, cudaFuncAttributeMaxDynamicSharedMemorySize, FUS_SMEM);

    cvt_kernel<<<dim3(4096, 5), 256>>>(x, Wq, Wk, Wv, Wo);

    qkv_tc<<<dim3(DMODEL/128, ROWS/128, 3), 256, GEMM_SMEM>>>(bq, bk, bv);

    attn_sums<<<dim3(SEQ/128, BH), 256, SUM_SMEM>>>(mask, (float*)pri);
    attn_fused<<<dim3(SEQ/128, BH), 512, FUS_SMEM>>>(mask, (const float*)pri, attout);

    gemmo_tc<<<dim3(DMODEL/128, ROWS/128), 256, GEMM_SMEM>>>(bo, x);
    ln_kernel<<<ROWS, 256>>>((const float*)ppre, gamma, beta, out);
}

// round 16
// speedup vs baseline: 1.0559x; 1.0244x over previous
#include <cuda_runtime.h>
#include <cuda_fp16.h>

#define DMODEL 1024
#define NHEADS 16
#define DK     64
#define BATCH  4
#define SEQ    2048
#define ROWS   (BATCH*SEQ)    // 8192
#define BH     (BATCH*NHEADS) // 64

// ---------------- scratch ----------------
__device__ __half   g_xh[(size_t)ROWS*DMODEL];
__device__ unsigned g_whq[(size_t)512*DMODEL];
__device__ unsigned g_whk[(size_t)512*DMODEL];
__device__ unsigned g_whv[(size_t)512*DMODEL];
__device__ unsigned g_who[(size_t)512*DMODEL];
__device__ __half   g_qh[(size_t)BH*SEQ*DK];
__device__ __half   g_kh[(size_t)BH*SEQ*DK];
__device__ __half   g_vh[(size_t)BH*SEQ*DK];
__device__ __half   g_ch[(size_t)ROWS*DMODEL];
__device__ float    g_pre[(size_t)ROWS*DMODEL];
__device__ float    g_rinv[(size_t)BH*SEQ];

// ---------------- helpers ----------------
__device__ __forceinline__ unsigned f2h2(float a, float b) {
    __half2 h = __floats2half2_rn(a, b);
    return *(unsigned*)&h;
}
__device__ __forceinline__ void mma16(float* c, const unsigned* a, const unsigned* b) {
    asm volatile(
        "mma.sync.aligned.m16n8k16.row.col.f32.f16.f16.f32 "
        "{%0,%1,%2,%3}, {%4,%5,%6,%7}, {%8,%9}, {%0,%1,%2,%3};"
        : "+f"(c[0]), "+f"(c[1]), "+f"(c[2]), "+f"(c[3])
        : "r"(a[0]), "r"(a[1]), "r"(a[2]), "r"(a[3]), "r"(b[0]), "r"(b[1]));
}
__device__ __forceinline__ unsigned sptr(const void* p) {
    return (unsigned)__cvta_generic_to_shared(p);
}
__device__ __forceinline__ void ldsm4(unsigned* r, unsigned a) {
    asm volatile("ldmatrix.sync.aligned.m8n8.x4.shared.b16 {%0,%1,%2,%3}, [%4];"
        : "=r"(r[0]), "=r"(r[1]), "=r"(r[2]), "=r"(r[3]) : "r"(a));
}
__device__ __forceinline__ void ldsm4t(unsigned* r, unsigned a) {
    asm volatile("ldmatrix.sync.aligned.m8n8.x4.trans.shared.b16 {%0,%1,%2,%3}, [%4];"
        : "=r"(r[0]), "=r"(r[1]), "=r"(r[2]), "=r"(r[3]) : "r"(a));
}
__device__ __forceinline__ void cpa16(void* s, const void* g) {
    unsigned ss = (unsigned)__cvta_generic_to_shared(s);
    asm volatile("cp.async.cg.shared.global [%0], [%1], 16;" :: "r"(ss), "l"(g));
}
__device__ __forceinline__ void cpcommit() { asm volatile("cp.async.commit_group;" ::: "memory"); }
__device__ __forceinline__ void cpwait1()  { asm volatile("cp.async.wait_group 1;" ::: "memory"); }
__device__ __forceinline__ void cpwait0()  { asm volatile("cp.async.wait_group 0;" ::: "memory"); }
__device__ __forceinline__ void stcs2(float* p, float a, float b) {
    asm volatile("st.global.cs.v2.f32 [%0], {%1,%2};" :: "l"(p), "f"(a), "f"(b) : "memory");
}

// ---------------- convert: x -> half, W -> k-pair-interleaved half2 ----------------
__global__ __launch_bounds__(256) void cvt_kernel(
    const float* __restrict__ x,
    const float* __restrict__ Wq, const float* __restrict__ Wk,
    const float* __restrict__ Wv, const float* __restrict__ Wo)
{
    int tid = threadIdx.x;
    if (blockIdx.y == 0) {
        size_t i = ((size_t)blockIdx.x*256 + tid)*8;
        float4 a = *(const float4*)(x + i);
        float4 b = *(const float4*)(x + i + 4);
        uint4 o = make_uint4(f2h2(a.x,a.y), f2h2(a.z,a.w), f2h2(b.x,b.y), f2h2(b.z,b.w));
        *(uint4*)(g_xh + i) = o;
    } else {
        int idx = blockIdx.x*256 + tid;
        if (idx >= 512*256) return;
        const float* W; unsigned* wh;
        if      (blockIdx.y == 1) { W = Wq; wh = g_whq; }
        else if (blockIdx.y == 2) { W = Wk; wh = g_whk; }
        else if (blockIdx.y == 3) { W = Wv; wh = g_whv; }
        else                      { W = Wo; wh = g_who; }
        int kp = idx >> 8, c4 = (idx & 255)*4;
        float4 r0 = *(const float4*)(W + (size_t)(2*kp    )*DMODEL + c4);
        float4 r1 = *(const float4*)(W + (size_t)(2*kp + 1)*DMODEL + c4);
        uint4 o = make_uint4(f2h2(r0.x,r1.x), f2h2(r0.y,r1.y), f2h2(r0.z,r1.z), f2h2(r0.w,r1.w));
        *(uint4*)(wh + (size_t)kp*DMODEL + c4) = o;
    }
}

// ---------------- GEMM: 128x128 tile, k-chunk 64, 3-buffer cp.async ----------------
#define APSTR 36
#define BPSTR 136
#define ABUF (128*APSTR)
#define BBUF (32*BPSTR)
#define GEMM_SMEM (3*(ABUF + BBUF)*4)

__device__ __forceinline__ void gemm5(
    const __half* __restrict__ Ah, const unsigned* __restrict__ Wh,
    const float* __restrict__ bias, const float* __restrict__ resid,
    float* outf, __half* outh, float scale,
    unsigned* sm, int brow, int bcol)
{
    const int tid  = threadIdx.x;
    const int warp = tid >> 5, lane = tid & 31;
    const int g    = lane >> 2, t = lane & 3;
    const int wm   = warp >> 2, wn = warp & 3;

    auto load = [&](int cc) {
        unsigned* Ad = sm + (cc % 3)*(ABUF + BBUF);
        unsigned* Bd = Ad + ABUF;
        int kt = cc * 64;
        #pragma unroll
        for (int j = 0; j < 4; j++) {
            int idx = tid + 256*j;
            int r = idx >> 3, seg = idx & 7;
            cpa16(Ad + r*APSTR + seg*4, Ah + (size_t)(brow + r)*DMODEL + kt + seg*8);
        }
        #pragma unroll
        for (int j = 0; j < 4; j++) {
            int idx = tid + 256*j;
            int kp = idx >> 5, seg = idx & 31;
            cpa16(Bd + kp*BPSTR + seg*4, Wh + (size_t)(kt/2 + kp)*DMODEL + bcol + seg*4);
        }
        cpcommit();
    };

    float c[4][4][4];
    #pragma unroll
    for (int mt = 0; mt < 4; mt++)
        #pragma unroll
        for (int nt = 0; nt < 4; nt++)
            #pragma unroll
            for (int i = 0; i < 4; i++) c[mt][nt][i] = 0.f;

    load(0); load(1);

    for (int cc = 0; cc < 16; cc++) {
        if (cc < 15) cpwait1(); else cpwait0();
        __syncthreads();
        if (cc + 2 < 16) load(cc + 2);
        const unsigned* As = sm + (cc % 3)*(ABUF + BBUF);
        const unsigned* Bs = As + ABUF;

        #pragma unroll
        for (int ks = 0; ks < 4; ks++) {
            int k0 = ks*8;
            unsigned bf[4][2];
            #pragma unroll
            for (int nt = 0; nt < 4; nt++) {
                int col = wn*32 + nt*8 + g;
                bf[nt][0] = Bs[(k0 + t    )*BPSTR + col];
                bf[nt][1] = Bs[(k0 + t + 4)*BPSTR + col];
            }
            #pragma unroll
            for (int mt = 0; mt < 4; mt++) {
                int r0 = wm*64 + mt*16 + g;
                unsigned af[4] = {As[r0*APSTR + k0 + t], As[(r0+8)*APSTR + k0 + t],
                                  As[r0*APSTR + k0 + t + 4], As[(r0+8)*APSTR + k0 + t + 4]};
                #pragma unroll
                for (int nt = 0; nt < 4; nt++) mma16(c[mt][nt], af, bf[nt]);
            }
        }
    }

    #pragma unroll
    for (int mt = 0; mt < 4; mt++)
        #pragma unroll
        for (int nt = 0; nt < 4; nt++)
            #pragma unroll
            for (int half = 0; half < 2; half++) {
                int row = brow + wm*64 + mt*16 + g + half*8;
                int col = bcol + wn*32 + nt*8 + 2*t;
                float v0 = c[mt][nt][half*2 + 0] + bias[col];
                float v1 = c[mt][nt][half*2 + 1] + bias[col + 1];
                if (outh) {
                    v0 *= scale; v1 *= scale;
                    int b = row >> 11, s = row & (SEQ-1);
                    int h = col >> 6,  d = col & (DK-1);
                    *(unsigned*)(outh + (size_t)((b*NHEADS + h)*SEQ + s)*DK + d) = f2h2(v0, v1);
                } else {
                    const float* rp = resid + (size_t)row*DMODEL + col;
                    float2 ov = make_float2(v0 + rp[0], v1 + rp[1]);
                    *(float2*)(outf + (size_t)row*DMODEL + col) = ov;
                }
            }
}

__global__ __launch_bounds__(256, 2) void qkv_tc(
    const float* __restrict__ bq, const float* __restrict__ bk, const float* __restrict__ bv)
{
    extern __shared__ unsigned gsm[];
    const unsigned* Wh; const float* bias; __half* outh; float scale;
    if (blockIdx.z == 0)      { Wh = g_whq; bias = bq; outh = g_qh; scale = 0.125f; }
    else if (blockIdx.z == 1) { Wh = g_whk; bias = bk; outh = g_kh; scale = 1.0f; }
    else                      { Wh = g_whv; bias = bv; outh = g_vh; scale = 1.0f; }
    gemm5(g_xh, Wh, bias, nullptr, nullptr, outh, scale, gsm,
          blockIdx.y * 128, blockIdx.x * 128);
}

__global__ __launch_bounds__(256, 2) void gemmo_tc(
    const float* __restrict__ bo, const float* __restrict__ resid)
{
    extern __shared__ unsigned gsm[];
    gemm5(g_ch, g_who, bo, resid, g_pre, nullptr, 1.0f, gsm,
          blockIdx.y * 128, blockIdx.x * 128);
}

// ---------------- pass A: row sums of exp(QK^T)*mask ----------------
#define QPSTR 36
#define KBUF  (128*QPSTR)
#define SUM_SMEM ((KBUF + 3*KBUF + SEQ + 512)*4)

__global__ __launch_bounds__(256, 2) void attn_sums(
    const int* __restrict__ mask, float* __restrict__ rinvg)
{
    extern __shared__ unsigned sm_[];
    unsigned* Qs   = sm_;
    unsigned* Kb0  = Qs + KBUF;
    float*    mskf = (float*)(Kb0 + 3*KBUF);
    float*    red  = mskf + SEQ;
    const unsigned Qbase  = sptr(Qs);
    const unsigned Kbase0 = sptr(Kb0);

    const int tid  = threadIdx.x;
    const int warp = tid >> 5, lane = tid & 31;
    const int g    = lane >> 2, t = lane & 3;
    const int wm   = warp >> 2, wn = warp & 3;
    const int q0   = blockIdx.x * 128;
    const int bh   = blockIdx.y;
    const int b    = bh >> 4;
    const __half* Qh = g_qh + (size_t)bh*SEQ*DK;
    const __half* Kh = g_kh + (size_t)bh*SEQ*DK;

    auto loadK = [&](int cc) {
        unsigned* Kd = Kb0 + (cc % 3)*KBUF;
        int kc = cc * 128;
        #pragma unroll
        for (int j = 0; j < 4; j++) {
            int idx = tid + 256*j;
            int r = idx >> 3, seg = idx & 7;
            cpa16(Kd + r*QPSTR + seg*4, Kh + (size_t)(kc + r)*DK + seg*8);
        }
        cpcommit();
    };

    #pragma unroll
    for (int j = 0; j < 4; j++) {
        int idx = tid + 256*j;
        int r = idx >> 3, seg = idx & 7;
        cpa16(Qs + r*QPSTR + seg*4, Qh + (size_t)(q0 + r)*DK + seg*8);
    }
    loadK(0); loadK(1);

    for (int i = tid; i < SEQ; i += 256) mskf[i] = mask[b*SEQ + i] ? 1.f : 0.f;

    float ps[4][2];
    #pragma unroll
    for (int mt = 0; mt < 4; mt++) { ps[mt][0] = 0.f; ps[mt][1] = 0.f; }

    for (int cc = 0; cc < 16; cc++) {
        if (cc < 15) cpwait1(); else cpwait0();
        __syncthreads();
        if (cc + 2 < 16) loadK(cc + 2);
        const unsigned Kbase = Kbase0 + (unsigned)((cc % 3)*KBUF)*4;
        int kc = cc * 128;

        float acc[4][4][4];
        #pragma unroll
        for (int mt = 0; mt < 4; mt++)
            #pragma unroll
            for (int nt = 0; nt < 4; nt++)
                #pragma unroll
                for (int i = 0; i < 4; i++) acc[mt][nt][i] = 0.f;

        #pragma unroll
        for (int ks = 0; ks < 4; ks++) {
            unsigned bf[4][2];
            #pragma unroll
            for (int ntp = 0; ntp < 2; ntp++) {
                unsigned rr[4];
                int key = wn*32 + ntp*16 + (lane & 7) + ((lane & 16) ? 8 : 0);
                unsigned a = Kbase + (unsigned)(key*QPSTR + ks*8)*4 + ((lane >> 3) & 1)*16;
                ldsm4(rr, a);
                bf[2*ntp][0] = rr[0]; bf[2*ntp][1] = rr[1];
                bf[2*ntp+1][0] = rr[2]; bf[2*ntp+1][1] = rr[3];
            }
            #pragma unroll
            for (int mt = 0; mt < 4; mt++) {
                unsigned af[4];
                unsigned a = Qbase + (unsigned)((wm*64 + mt*16 + (lane & 15))*QPSTR + ks*8)*4
                           + (lane >> 4)*16;
                ldsm4(af, a);
                #pragma unroll
                for (int nt = 0; nt < 4; nt++) mma16(acc[mt][nt], af, bf[nt]);
            }
        }
        #pragma unroll
        for (int mt = 0; mt < 4; mt++)
            #pragma unroll
            for (int nt = 0; nt < 4; nt++)
                #pragma unroll
                for (int half = 0; half < 2; half++) {
                    int col = kc + wn*32 + nt*8 + 2*t;
                    ps[mt][half] += __expf(acc[mt][nt][half*2 + 0]) * mskf[col]
                                  + __expf(acc[mt][nt][half*2 + 1]) * mskf[col + 1];
                }
    }

    #pragma unroll
    for (int mt = 0; mt < 4; mt++)
        #pragma unroll
        for (int half = 0; half < 2; half++) {
            float v = ps[mt][half];
            v += __shfl_xor_sync(0xffffffffu, v, 1);
            v += __shfl_xor_sync(0xffffffffu, v, 2);
            if (t == 0) red[wn*128 + wm*64 + mt*16 + g + half*8] = v;
        }
    __syncthreads();
    if (tid < 128) {
        float s = red[tid] + red[128 + tid] + red[256 + tid] + red[384 + tid];
        rinvg[(size_t)bh*SEQ + q0 + tid] = 1.0f / s;
    }
}

// ---------------- pass B: recompute QK, direct att write, register PV ----------------
#define FKBUF (64*QPSTR)
#define RSTR  66
#define FUS_SMEM ((128*QPSTR + 3*FKBUF + 3*FKBUF + SEQ + 128 + 128*RSTR)*4)

__global__ __launch_bounds__(512, 1) void attn_fused(
    const int* __restrict__ mask, const float* __restrict__ rinvg,
    float* __restrict__ attout)
{
    extern __shared__ unsigned sm_[];
    unsigned* Qs   = sm_;                         // [128][QPSTR]
    unsigned* Kb0  = Qs + 128*QPSTR;              // 3 x [64][QPSTR]
    unsigned* Vb0  = Kb0 + 3*FKBUF;               // 3 x [64][QPSTR]
    float*    mskf = (float*)(Vb0 + 3*FKBUF);     // [SEQ]
    float*    rinv = mskf + SEQ;                  // [128]
    float*    red  = rinv + 128;                  // [128][RSTR]
    const unsigned Qbase  = sptr(Qs);
    const unsigned Kbase0 = sptr(Kb0);
    const unsigned Vbase0 = sptr(Vb0);

    const int tid  = threadIdx.x;
    const int warp = tid >> 5, lane = tid & 31;
    const int g    = lane >> 2, t = lane & 3;
    const int wm   = warp >> 1, wn = warp & 1;     // 8 x 2
    const int q0   = blockIdx.x * 128;
    const int bh   = blockIdx.y;
    const int b    = bh >> 4, h = bh & 15;
    const __half* Qh = g_qh + (size_t)bh*SEQ*DK;
    const __half* Kh = g_kh + (size_t)bh*SEQ*DK;
    const __half* Vh = g_vh + (size_t)bh*SEQ*DK;

    auto loadKV = [&](int cc) {
        unsigned* Kd = Kb0 + (cc % 3)*FKBUF;
        unsigned* Vd = Vb0 + (cc % 3)*FKBUF;
        int kc = cc * 64;
        {
            int r = tid >> 3, seg = tid & 7;
            cpa16(Kd + r*QPSTR + seg*4, Kh + (size_t)(kc + r)*DK + seg*8);
            cpa16(Vd + r*QPSTR + seg*4, Vh + (size_t)(kc + r)*DK + seg*8);
        }
        cpcommit();
    };

    #pragma unroll
    for (int j = 0; j < 2; j++) {
        int idx = tid + 512*j;
        int r = idx >> 3, seg = idx & 7;
        cpa16(Qs + r*QPSTR + seg*4, Qh + (size_t)(q0 + r)*DK + seg*8);
    }
    loadKV(0); loadKV(1);

    for (int i = tid; i < SEQ; i += 512) mskf[i] = mask[b*SEQ + i] ? 1.f : 0.f;
    if (tid < 128) rinv[tid] = rinvg[(size_t)bh*SEQ + q0 + tid];

    float d[8][4];
    #pragma unroll
    for (int nt = 0; nt < 8; nt++)
        #pragma unroll
        for (int i = 0; i < 4; i++) d[nt][i] = 0.f;

    const int r0 = wm*16 + g;
    float* attrow0 = attout + ((size_t)bh*SEQ + q0 + r0)*SEQ;
    float* attrow1 = attout + ((size_t)bh*SEQ + q0 + r0 + 8)*SEQ;
    const float iv0 = rinvg[(size_t)bh*SEQ + q0 + r0];
    const float iv1 = rinvg[(size_t)bh*SEQ + q0 + r0 + 8];

    // wait for Q (+ chunk 0) and hoist Q fragments into registers (chunk-invariant)
    cpwait1();
    __syncthreads();
    unsigned qf[4][4];
    #pragma unroll
    for (int ks = 0; ks < 4; ks++) {
        unsigned a = Qbase + (unsigned)((wm*16 + (lane & 15))*QPSTR + ks*8)*4
                   + (lane >> 4)*16;
        ldsm4(qf[ks], a);
    }

    for (int cc = 0; cc < 32; cc++) {
        if (cc > 0) {
            if (cc < 31) cpwait1(); else cpwait0();
            __syncthreads();
        }
        if (cc + 2 < 32) loadKV(cc + 2);
        const unsigned Kbase = Kbase0 + (unsigned)((cc % 3)*FKBUF)*4;
        const unsigned Vbase = Vbase0 + (unsigned)((cc % 3)*FKBUF)*4;
        int kc = cc * 64;

        // ---- QK: 16 rows x 32 keys ----
        float s[4][4];
        #pragma unroll
        for (int nt = 0; nt < 4; nt++)
            #pragma unroll
            for (int i = 0; i < 4; i++) s[nt][i] = 0.f;

        #pragma unroll
        for (int ks = 0; ks < 4; ks++) {
            unsigned bf[4][2];
            #pragma unroll
            for (int ntp = 0; ntp < 2; ntp++) {
                unsigned rr[4];
                int key = wn*32 + ntp*16 + (lane & 7) + ((lane & 16) ? 8 : 0);
                unsigned a = Kbase + (unsigned)(key*QPSTR + ks*8)*4 + ((lane >> 3) & 1)*16;
                ldsm4(rr, a);
                bf[2*ntp][0] = rr[0]; bf[2*ntp][1] = rr[1];
                bf[2*ntp+1][0] = rr[2]; bf[2*ntp+1][1] = rr[3];
            }
            #pragma unroll
            for (int nt = 0; nt < 4; nt++) mma16(s[nt], qf[ks], bf[nt]);
        }

        // ---- epilogue: e in registers, att written directly (streaming) ----
        float e[4][4];
        #pragma unroll
        for (int nt = 0; nt < 4; nt++) {
            int col = wn*32 + nt*8 + 2*t;
            float2 m = *(const float2*)(mskf + kc + col);
            e[nt][0] = __expf(s[nt][0]) * m.x * iv0;
            e[nt][1] = __expf(s[nt][1]) * m.y * iv0;
            e[nt][2] = __expf(s[nt][2]) * m.x * iv1;
            e[nt][3] = __expf(s[nt][3]) * m.y * iv1;
            stcs2(attrow0 + kc + col, e[nt][0], e[nt][1]);
            stcs2(attrow1 + kc + col, e[nt][2], e[nt][3]);
        }

        // ---- PV: A-fragments from registers; V via ldmatrix.trans ----
        #pragma unroll
        for (int ks2 = 0; ks2 < 2; ks2++) {
            unsigned af[4] = {f2h2(e[ks2*2][0],   e[ks2*2][1]),
                              f2h2(e[ks2*2][2],   e[ks2*2][3]),
                              f2h2(e[ks2*2+1][0], e[ks2*2+1][1]),
                              f2h2(e[ks2*2+1][2], e[ks2*2+1][3])};
            #pragma unroll
            for (int nt2 = 0; nt2 < 4; nt2++) {
                unsigned rr[4];
                unsigned a = Vbase
                    + (unsigned)((wn*32 + ks2*16 + (lane & 15))*QPSTR)*4
                    + (unsigned)(nt2*16)*2 + (lane >> 4)*16;
                ldsm4t(rr, a);
                mma16(d[nt2*2    ], af, rr);
                mma16(d[nt2*2 + 1], af, rr + 2);
            }
        }
    }

    // ---- cross-warp key-half reduction + ctx write ----
    __syncthreads();
    if (wn == 1) {
        #pragma unroll
        for (int nt = 0; nt < 8; nt++)
            #pragma unroll
            for (int half = 0; half < 2; half++) {
                int row = wm*16 + g + half*8;
                int col = nt*8 + 2*t;
                *(float2*)(red + row*RSTR + col) =
                    make_float2(d[nt][half*2 + 0], d[nt][half*2 + 1]);
            }
    }
    __syncthreads();
    if (wn == 0) {
        #pragma unroll
        for (int nt = 0; nt < 8; nt++)
            #pragma unroll
            for (int half = 0; half < 2; half++) {
                int row = wm*16 + g + half*8;
                int col = nt*8 + 2*t;
                float2 o = *(const float2*)(red + row*RSTR + col);
                float v0 = d[nt][half*2 + 0] + o.x;
                float v1 = d[nt][half*2 + 1] + o.y;
                *(unsigned*)(g_ch + (size_t)(b*SEQ + q0 + row)*DMODEL + h*DK + col) = f2h2(v0, v1);
            }
    }
}

// ---------------- LayerNorm ----------------
__global__ __launch_bounds__(256) void ln_kernel(
    const float* __restrict__ pre, const float* __restrict__ gamma,
    const float* __restrict__ beta, float* __restrict__ out)
{
    const int tid = threadIdx.x;
    const int row = blockIdx.x;
    float4 v = ((const float4*)(pre + (size_t)row*DMODEL))[tid];
    float s  = v.x + v.y + v.z + v.w;
    float s2 = v.x*v.x + v.y*v.y + v.z*v.z + v.w*v.w;
    #pragma unroll
    for (int o = 16; o > 0; o >>= 1) {
        s  += __shfl_xor_sync(0xffffffffu, s,  o);
        s2 += __shfl_xor_sync(0xffffffffu, s2, o);
    }
    __shared__ float ws[8], ws2[8];
    __shared__ float mu_s, r_s;
    if ((tid & 31) == 0) { ws[tid >> 5] = s; ws2[tid >> 5] = s2; }
    __syncthreads();
    if (tid == 0) {
        float tt = 0.f, t2 = 0.f;
        #pragma unroll
        for (int i = 0; i < 8; i++) { tt += ws[i]; t2 += ws2[i]; }
        float mu  = tt * (1.0f/DMODEL);
        float var = t2 * (1.0f/DMODEL) - mu*mu;
        mu_s = mu;
        r_s  = rsqrtf(var + 1e-5f);
    }
    __syncthreads();
    float mu = mu_s, r = r_s;
    float4 gm = ((const float4*)gamma)[tid];
    float4 be = ((const float4*)beta)[tid];
    float4 o;
    o.x = (v.x - mu)*r*gm.x + be.x;
    o.y = (v.y - mu)*r*gm.y + be.y;
    o.z = (v.z - mu)*r*gm.z + be.z;
    o.w = (v.w - mu)*r*gm.w + be.w;
    ((float4*)(out + (size_t)row*DMODEL))[tid] = o;
}

// ---------------- launch ----------------
extern "C" void kernel_launch(void* const* d_in, const int* in_sizes, int n_in,
                              void* d_out, int out_size)
{
    const float* x     = (const float*)d_in[0];
    const int*   mask  = (const int*)  d_in[1];
    const float* Wq    = (const float*)d_in[2];
    const float* bq    = (const float*)d_in[3];
    const float* Wk    = (const float*)d_in[4];
    const float* bk    = (const float*)d_in[5];
    const float* Wv    = (const float*)d_in[6];
    const float* bv    = (const float*)d_in[7];
    const float* Wo    = (const float*)d_in[8];
    const float* bo    = (const float*)d_in[9];
    const float* gamma = (const float*)d_in[10];
    const float* beta  = (const float*)d_in[11];
    float* out = (float*)d_out;

    void *ppre, *pri;
    cudaGetSymbolAddress(&ppre, g_pre);
    cudaGetSymbolAddress(&pri,  g_rinv);

    const long long OUT_ELEMS = (long long)ROWS * DMODEL;
    float* attout = out + OUT_ELEMS;

    cudaFuncSetAttribute(qkv_tc,     cudaFuncAttributeMaxDynamicSharedMemorySize, GEMM_SMEM);
    cudaFuncSetAttribute(gemmo_tc,   cudaFuncAttributeMaxDynamicSharedMemorySize, GEMM_SMEM);
    cudaFuncSetAttribute(attn_sums,  cudaFuncAttributeMaxDynamicSharedMemorySize, SUM_SMEM);
    cudaFuncSetAttribute(attn_fused, cudaFuncAttributeMaxDynamicSharedMemorySize, FUS_SMEM);

    cvt_kernel<<<dim3(4096, 5), 256>>>(x, Wq, Wk, Wv, Wo);

    qkv_tc<<<dim3(DMODEL/128, ROWS/128, 3), 256, GEMM_SMEM>>>(bq, bk, bv);

    attn_sums<<<dim3(SEQ/128, BH), 256, SUM_SMEM>>>(mask, (float*)pri);
    attn_fused<<<dim3(SEQ/128, BH), 512, FUS_SMEM>>>(mask, (const float*)pri, attout);

    gemmo_tc<<<dim3(DMODEL/128, ROWS/128), 256, GEMM_SMEM>>>(bo, x);
    ln_kernel<<<ROWS, 256>>>((const float*)ppre, gamma, beta, out);
}

// round 17
// speedup vs baseline: 1.0641x; 1.0078x over previous
#include <cuda_runtime.h>
#include <cuda_fp16.h>

#define DMODEL 1024
#define NHEADS 16
#define DK     64
#define BATCH  4
#define SEQ    2048
#define ROWS   (BATCH*SEQ)    // 8192
#define BH     (BATCH*NHEADS) // 64

// ---------------- scratch ----------------
__device__ __half   g_xh[(size_t)ROWS*DMODEL];
__device__ unsigned g_whq[(size_t)512*DMODEL];
__device__ unsigned g_whk[(size_t)512*DMODEL];
__device__ unsigned g_whv[(size_t)512*DMODEL];
__device__ unsigned g_who[(size_t)512*DMODEL];
__device__ __half   g_qh[(size_t)BH*SEQ*DK];
__device__ __half   g_kh[(size_t)BH*SEQ*DK];
__device__ __half   g_vh[(size_t)BH*SEQ*DK];
__device__ __half   g_ch[(size_t)ROWS*DMODEL];
__device__ float    g_pre[(size_t)ROWS*DMODEL];
__device__ float    g_rinv[(size_t)BH*SEQ];

// ---------------- helpers ----------------
__device__ __forceinline__ unsigned f2h2(float a, float b) {
    __half2 h = __floats2half2_rn(a, b);
    return *(unsigned*)&h;
}
__device__ __forceinline__ void mma16(float* c, const unsigned* a, const unsigned* b) {
    asm volatile(
        "mma.sync.aligned.m16n8k16.row.col.f32.f16.f16.f32 "
        "{%0,%1,%2,%3}, {%4,%5,%6,%7}, {%8,%9}, {%0,%1,%2,%3};"
        : "+f"(c[0]), "+f"(c[1]), "+f"(c[2]), "+f"(c[3])
        : "r"(a[0]), "r"(a[1]), "r"(a[2]), "r"(a[3]), "r"(b[0]), "r"(b[1]));
}
__device__ __forceinline__ unsigned sptr(const void* p) {
    return (unsigned)__cvta_generic_to_shared(p);
}
__device__ __forceinline__ void ldsm4(unsigned* r, unsigned a) {
    asm volatile("ldmatrix.sync.aligned.m8n8.x4.shared.b16 {%0,%1,%2,%3}, [%4];"
        : "=r"(r[0]), "=r"(r[1]), "=r"(r[2]), "=r"(r[3]) : "r"(a));
}
__device__ __forceinline__ void ldsm4t(unsigned* r, unsigned a) {
    asm volatile("ldmatrix.sync.aligned.m8n8.x4.trans.shared.b16 {%0,%1,%2,%3}, [%4];"
        : "=r"(r[0]), "=r"(r[1]), "=r"(r[2]), "=r"(r[3]) : "r"(a));
}
__device__ __forceinline__ void cpa16(void* s, const void* g) {
    unsigned ss = (unsigned)__cvta_generic_to_shared(s);
    asm volatile("cp.async.cg.shared.global [%0], [%1], 16;" :: "r"(ss), "l"(g));
}
__device__ __forceinline__ void cpcommit() { asm volatile("cp.async.commit_group;" ::: "memory"); }
__device__ __forceinline__ void cpwait1()  { asm volatile("cp.async.wait_group 1;" ::: "memory"); }
__device__ __forceinline__ void cpwait0()  { asm volatile("cp.async.wait_group 0;" ::: "memory"); }
__device__ __forceinline__ void stcs2(float* p, float a, float b) {
    asm volatile("st.global.cs.v2.f32 [%0], {%1,%2};" :: "l"(p), "f"(a), "f"(b) : "memory");
}

// ---------------- convert: x -> half, W -> k-pair-interleaved half2 ----------------
__global__ __launch_bounds__(256) void cvt_kernel(
    const float* __restrict__ x,
    const float* __restrict__ Wq, const float* __restrict__ Wk,
    const float* __restrict__ Wv, const float* __restrict__ Wo)
{
    int tid = threadIdx.x;
    if (blockIdx.y == 0) {
        size_t i = ((size_t)blockIdx.x*256 + tid)*8;
        float4 a = *(const float4*)(x + i);
        float4 b = *(const float4*)(x + i + 4);
        uint4 o = make_uint4(f2h2(a.x,a.y), f2h2(a.z,a.w), f2h2(b.x,b.y), f2h2(b.z,b.w));
        *(uint4*)(g_xh + i) = o;
    } else {
        int idx = blockIdx.x*256 + tid;
        if (idx >= 512*256) return;
        const float* W; unsigned* wh;
        if      (blockIdx.y == 1) { W = Wq; wh = g_whq; }
        else if (blockIdx.y == 2) { W = Wk; wh = g_whk; }
        else if (blockIdx.y == 3) { W = Wv; wh = g_whv; }
        else                      { W = Wo; wh = g_who; }
        int kp = idx >> 8, c4 = (idx & 255)*4;
        float4 r0 = *(const float4*)(W + (size_t)(2*kp    )*DMODEL + c4);
        float4 r1 = *(const float4*)(W + (size_t)(2*kp + 1)*DMODEL + c4);
        uint4 o = make_uint4(f2h2(r0.x,r1.x), f2h2(r0.y,r1.y), f2h2(r0.z,r1.z), f2h2(r0.w,r1.w));
        *(uint4*)(wh + (size_t)kp*DMODEL + c4) = o;
    }
}

// ---------------- GEMM: 128x128 tile, k-chunk 64, 3-buffer cp.async ----------------
#define APSTR 36
#define BPSTR 136
#define ABUF (128*APSTR)
#define BBUF (32*BPSTR)
#define GEMM_SMEM (3*(ABUF + BBUF)*4)

__device__ __forceinline__ void gemm5(
    const __half* __restrict__ Ah, const unsigned* __restrict__ Wh,
    const float* __restrict__ bias, const float* __restrict__ resid,
    float* outf, __half* outh, float scale,
    unsigned* sm, int brow, int bcol)
{
    const int tid  = threadIdx.x;
    const int warp = tid >> 5, lane = tid & 31;
    const int g    = lane >> 2, t = lane & 3;
    const int wm   = warp >> 2, wn = warp & 3;
    const unsigned Sbase = sptr(sm);

    auto load = [&](int cc) {
        unsigned* Ad = sm + (cc % 3)*(ABUF + BBUF);
        unsigned* Bd = Ad + ABUF;
        int kt = cc * 64;
        #pragma unroll
        for (int j = 0; j < 4; j++) {
            int idx = tid + 256*j;
            int r = idx >> 3, seg = idx & 7;
            cpa16(Ad + r*APSTR + seg*4, Ah + (size_t)(brow + r)*DMODEL + kt + seg*8);
        }
        #pragma unroll
        for (int j = 0; j < 4; j++) {
            int idx = tid + 256*j;
            int kp = idx >> 5, seg = idx & 31;
            cpa16(Bd + kp*BPSTR + seg*4, Wh + (size_t)(kt/2 + kp)*DMODEL + bcol + seg*4);
        }
        cpcommit();
    };

    float c[4][4][4];
    #pragma unroll
    for (int mt = 0; mt < 4; mt++)
        #pragma unroll
        for (int nt = 0; nt < 4; nt++)
            #pragma unroll
            for (int i = 0; i < 4; i++) c[mt][nt][i] = 0.f;

    load(0); load(1);

    for (int cc = 0; cc < 16; cc++) {
        if (cc < 15) cpwait1(); else cpwait0();
        __syncthreads();
        if (cc + 2 < 16) load(cc + 2);
        const unsigned Abase = Sbase + (unsigned)((cc % 3)*(ABUF + BBUF))*4;
        const unsigned* Bs = sm + (cc % 3)*(ABUF + BBUF) + ABUF;

        #pragma unroll
        for (int ks = 0; ks < 4; ks++) {
            int k0 = ks*8;
            unsigned bf[4][2];
            #pragma unroll
            for (int nt = 0; nt < 4; nt++) {
                int col = wn*32 + nt*8 + g;
                bf[nt][0] = Bs[(k0 + t    )*BPSTR + col];
                bf[nt][1] = Bs[(k0 + t + 4)*BPSTR + col];
            }
            #pragma unroll
            for (int mt = 0; mt < 4; mt++) {
                unsigned af[4];
                unsigned a = Abase + (unsigned)((wm*64 + mt*16 + (lane & 15))*APSTR + k0)*4
                           + (lane >> 4)*16;
                ldsm4(af, a);
                #pragma unroll
                for (int nt = 0; nt < 4; nt++) mma16(c[mt][nt], af, bf[nt]);
            }
        }
    }

    #pragma unroll
    for (int mt = 0; mt < 4; mt++)
        #pragma unroll
        for (int nt = 0; nt < 4; nt++)
            #pragma unroll
            for (int half = 0; half < 2; half++) {
                int row = brow + wm*64 + mt*16 + g + half*8;
                int col = bcol + wn*32 + nt*8 + 2*t;
                float v0 = c[mt][nt][half*2 + 0] + bias[col];
                float v1 = c[mt][nt][half*2 + 1] + bias[col + 1];
                if (outh) {
                    v0 *= scale; v1 *= scale;
                    int b = row >> 11, s = row & (SEQ-1);
                    int h = col >> 6,  d = col & (DK-1);
                    *(unsigned*)(outh + (size_t)((b*NHEADS + h)*SEQ + s)*DK + d) = f2h2(v0, v1);
                } else {
                    const float* rp = resid + (size_t)row*DMODEL + col;
                    float2 ov = make_float2(v0 + rp[0], v1 + rp[1]);
                    *(float2*)(outf + (size_t)row*DMODEL + col) = ov;
                }
            }
}

__global__ __launch_bounds__(256, 2) void qkv_tc(
    const float* __restrict__ bq, const float* __restrict__ bk, const float* __restrict__ bv)
{
    extern __shared__ unsigned gsm[];
    const unsigned* Wh; const float* bias; __half* outh; float scale;
    if (blockIdx.z == 0)      { Wh = g_whq; bias = bq; outh = g_qh; scale = 0.125f; }
    else if (blockIdx.z == 1) { Wh = g_whk; bias = bk; outh = g_kh; scale = 1.0f; }
    else                      { Wh = g_whv; bias = bv; outh = g_vh; scale = 1.0f; }
    gemm5(g_xh, Wh, bias, nullptr, nullptr, outh, scale, gsm,
          blockIdx.y * 128, blockIdx.x * 128);
}

__global__ __launch_bounds__(256, 2) void gemmo_tc(
    const float* __restrict__ bo, const float* __restrict__ resid)
{
    extern __shared__ unsigned gsm[];
    gemm5(g_ch, g_who, bo, resid, g_pre, nullptr, 1.0f, gsm,
          blockIdx.y * 128, blockIdx.x * 128);
}

// ---------------- pass A: row sums of exp(QK^T)*mask ----------------
#define QPSTR 36
#define KBUF  (128*QPSTR)
#define SUM_SMEM ((KBUF + 3*KBUF + SEQ + 512)*4)

__global__ __launch_bounds__(256, 2) void attn_sums(
    const int* __restrict__ mask, float* __restrict__ rinvg)
{
    extern __shared__ unsigned sm_[];
    unsigned* Qs   = sm_;
    unsigned* Kb0  = Qs + KBUF;
    float*    mskf = (float*)(Kb0 + 3*KBUF);
    float*    red  = mskf + SEQ;
    const unsigned Qbase  = sptr(Qs);
    const unsigned Kbase0 = sptr(Kb0);

    const int tid  = threadIdx.x;
    const int warp = tid >> 5, lane = tid & 31;
    const int g    = lane >> 2, t = lane & 3;
    const int wm   = warp >> 2, wn = warp & 3;
    const int q0   = blockIdx.x * 128;
    const int bh   = blockIdx.y;
    const int b    = bh >> 4;
    const __half* Qh = g_qh + (size_t)bh*SEQ*DK;
    const __half* Kh = g_kh + (size_t)bh*SEQ*DK;

    auto loadK = [&](int cc) {
        unsigned* Kd = Kb0 + (cc % 3)*KBUF;
        int kc = cc * 128;
        #pragma unroll
        for (int j = 0; j < 4; j++) {
            int idx = tid + 256*j;
            int r = idx >> 3, seg = idx & 7;
            cpa16(Kd + r*QPSTR + seg*4, Kh + (size_t)(kc + r)*DK + seg*8);
        }
        cpcommit();
    };

    #pragma unroll
    for (int j = 0; j < 4; j++) {
        int idx = tid + 256*j;
        int r = idx >> 3, seg = idx & 7;
        cpa16(Qs + r*QPSTR + seg*4, Qh + (size_t)(q0 + r)*DK + seg*8);
    }
    loadK(0); loadK(1);

    for (int i = tid; i < SEQ; i += 256) mskf[i] = mask[b*SEQ + i] ? 1.f : 0.f;

    float ps[4][2];
    #pragma unroll
    for (int mt = 0; mt < 4; mt++) { ps[mt][0] = 0.f; ps[mt][1] = 0.f; }

    for (int cc = 0; cc < 16; cc++) {
        if (cc < 15) cpwait1(); else cpwait0();
        __syncthreads();
        if (cc + 2 < 16) loadK(cc + 2);
        const unsigned Kbase = Kbase0 + (unsigned)((cc % 3)*KBUF)*4;
        int kc = cc * 128;

        float acc[4][4][4];
        #pragma unroll
        for (int mt = 0; mt < 4; mt++)
            #pragma unroll
            for (int nt = 0; nt < 4; nt++)
                #pragma unroll
                for (int i = 0; i < 4; i++) acc[mt][nt][i] = 0.f;

        #pragma unroll
        for (int ks = 0; ks < 4; ks++) {
            unsigned bf[4][2];
            #pragma unroll
            for (int ntp = 0; ntp < 2; ntp++) {
                unsigned rr[4];
                int key = wn*32 + ntp*16 + (lane & 7) + ((lane & 16) ? 8 : 0);
                unsigned a = Kbase + (unsigned)(key*QPSTR + ks*8)*4 + ((lane >> 3) & 1)*16;
                ldsm4(rr, a);
                bf[2*ntp][0] = rr[0]; bf[2*ntp][1] = rr[1];
                bf[2*ntp+1][0] = rr[2]; bf[2*ntp+1][1] = rr[3];
            }
            #pragma unroll
            for (int mt = 0; mt < 4; mt++) {
                unsigned af[4];
                unsigned a = Qbase + (unsigned)((wm*64 + mt*16 + (lane & 15))*QPSTR + ks*8)*4
                           + (lane >> 4)*16;
                ldsm4(af, a);
                #pragma unroll
                for (int nt = 0; nt < 4; nt++) mma16(acc[mt][nt], af, bf[nt]);
            }
        }
        #pragma unroll
        for (int mt = 0; mt < 4; mt++)
            #pragma unroll
            for (int nt = 0; nt < 4; nt++)
                #pragma unroll
                for (int half = 0; half < 2; half++) {
                    int col = kc + wn*32 + nt*8 + 2*t;
                    ps[mt][half] += __expf(acc[mt][nt][half*2 + 0]) * mskf[col]
                                  + __expf(acc[mt][nt][half*2 + 1]) * mskf[col + 1];
                }
    }

    #pragma unroll
    for (int mt = 0; mt < 4; mt++)
        #pragma unroll
        for (int half = 0; half < 2; half++) {
            float v = ps[mt][half];
            v += __shfl_xor_sync(0xffffffffu, v, 1);
            v += __shfl_xor_sync(0xffffffffu, v, 2);
            if (t == 0) red[wn*128 + wm*64 + mt*16 + g + half*8] = v;
        }
    __syncthreads();
    if (tid < 128) {
        float s = red[tid] + red[128 + tid] + red[256 + tid] + red[384 + tid];
        rinvg[(size_t)bh*SEQ + q0 + tid] = 1.0f / s;
    }
}

// ---------------- pass B: recompute QK, direct att write, register PV ----------------
// red aliases Qs (Q only needed for the one-time register hoist).
#define FKBUF (64*QPSTR)
#define RSTR  66
#define FUS_SMEM ((128*QPSTR + 3*FKBUF + 3*FKBUF + SEQ + 128)*4)

__global__ __launch_bounds__(512, 1) void attn_fused(
    const int* __restrict__ mask, const float* __restrict__ rinvg,
    float* __restrict__ attout)
{
    extern __shared__ unsigned sm_[];
    unsigned* Qs   = sm_;                         // [128][QPSTR]  (reused as red)
    unsigned* Kb0  = Qs + 128*QPSTR;              // 3 x [64][QPSTR]
    unsigned* Vb0  = Kb0 + 3*FKBUF;               // 3 x [64][QPSTR]
    float*    mskf = (float*)(Vb0 + 3*FKBUF);     // [SEQ]
    float*    rinv = mskf + SEQ;                  // [128]
    float*    red  = (float*)Qs;                  // [128][RSTR] aliases Qs (8448 < 4608? no)
    const unsigned Qbase  = sptr(Qs);
    const unsigned Kbase0 = sptr(Kb0);
    const unsigned Vbase0 = sptr(Vb0);

    const int tid  = threadIdx.x;
    const int warp = tid >> 5, lane = tid & 31;
    const int g    = lane >> 2, t = lane & 3;
    const int wm   = warp >> 1, wn = warp & 1;     // 8 x 2
    const int q0   = blockIdx.x * 128;
    const int bh   = blockIdx.y;
    const int b    = bh >> 4, h = bh & 15;
    const __half* Qh = g_qh + (size_t)bh*SEQ*DK;
    const __half* Kh = g_kh + (size_t)bh*SEQ*DK;
    const __half* Vh = g_vh + (size_t)bh*SEQ*DK;

    auto loadKV = [&](int cc) {
        unsigned* Kd = Kb0 + (cc % 3)*FKBUF;
        unsigned* Vd = Vb0 + (cc % 3)*FKBUF;
        int kc = cc * 64;
        {
            int r = tid >> 3, seg = tid & 7;
            cpa16(Kd + r*QPSTR + seg*4, Kh + (size_t)(kc + r)*DK + seg*8);
            cpa16(Vd + r*QPSTR + seg*4, Vh + (size_t)(kc + r)*DK + seg*8);
        }
        cpcommit();
    };

    #pragma unroll
    for (int j = 0; j < 2; j++) {
        int idx = tid + 512*j;
        int r = idx >> 3, seg = idx & 7;
        cpa16(Qs + r*QPSTR + seg*4, Qh + (size_t)(q0 + r)*DK + seg*8);
    }
    loadKV(0); loadKV(1);

    for (int i = tid; i < SEQ; i += 512) mskf[i] = mask[b*SEQ + i] ? 1.f : 0.f;
    if (tid < 128) rinv[tid] = rinvg[(size_t)bh*SEQ + q0 + tid];

    float d[8][4];
    #pragma unroll
    for (int nt = 0; nt < 8; nt++)
        #pragma unroll
        for (int i = 0; i < 4; i++) d[nt][i] = 0.f;

    const int r0 = wm*16 + g;
    float* attrow0 = attout + ((size_t)bh*SEQ + q0 + r0)*SEQ;
    float* attrow1 = attout + ((size_t)bh*SEQ + q0 + r0 + 8)*SEQ;
    const float iv0 = rinvg[(size_t)bh*SEQ + q0 + r0];
    const float iv1 = rinvg[(size_t)bh*SEQ + q0 + r0 + 8];

    // wait for Q (+ chunk 0) and hoist Q fragments into registers (chunk-invariant)
    cpwait1();
    __syncthreads();
    unsigned qf[4][4];
    #pragma unroll
    for (int ks = 0; ks < 4; ks++) {
        unsigned a = Qbase + (unsigned)((wm*16 + (lane & 15))*QPSTR + ks*8)*4
                   + (lane >> 4)*16;
        ldsm4(qf[ks], a);
    }
    __syncthreads();   // all warps done reading Qs before it is reused as red

    for (int cc = 0; cc < 32; cc++) {
        if (cc > 0) {
            if (cc < 31) cpwait1(); else cpwait0();
            __syncthreads();
        }
        if (cc + 2 < 32) loadKV(cc + 2);
        const unsigned Kbase = Kbase0 + (unsigned)((cc % 3)*FKBUF)*4;
        const unsigned Vbase = Vbase0 + (unsigned)((cc % 3)*FKBUF)*4;
        int kc = cc * 64;

        // ---- QK: 16 rows x 32 keys ----
        float s[4][4];
        #pragma unroll
        for (int nt = 0; nt < 4; nt++)
            #pragma unroll
            for (int i = 0; i < 4; i++) s[nt][i] = 0.f;

        #pragma unroll
        for (int ks = 0; ks < 4; ks++) {
            unsigned bf[4][2];
            #pragma unroll
            for (int ntp = 0; ntp < 2; ntp++) {
                unsigned rr[4];
                int key = wn*32 + ntp*16 + (lane & 7) + ((lane & 16) ? 8 : 0);
                unsigned a = Kbase + (unsigned)(key*QPSTR + ks*8)*4 + ((lane >> 3) & 1)*16;
                ldsm4(rr, a);
                bf[2*ntp][0] = rr[0]; bf[2*ntp][1] = rr[1];
                bf[2*ntp+1][0] = rr[2]; bf[2*ntp+1][1] = rr[3];
            }
            #pragma unroll
            for (int nt = 0; nt < 4; nt++) mma16(s[nt], qf[ks], bf[nt]);
        }

        // ---- epilogue: e in registers, att written directly (streaming) ----
        float e[4][4];
        #pragma unroll
        for (int nt = 0; nt < 4; nt++) {
            int col = wn*32 + nt*8 + 2*t;
            float2 m = *(const float2*)(mskf + kc + col);
            e[nt][0] = __expf(s[nt][0]) * m.x * iv0;
            e[nt][1] = __expf(s[nt][1]) * m.y * iv0;
            e[nt][2] = __expf(s[nt][2]) * m.x * iv1;
            e[nt][3] = __expf(s[nt][3]) * m.y * iv1;
            stcs2(attrow0 + kc + col, e[nt][0], e[nt][1]);
            stcs2(attrow1 + kc + col, e[nt][2], e[nt][3]);
        }

        // ---- PV: A-fragments from registers; V via ldmatrix.trans ----
        #pragma unroll
        for (int ks2 = 0; ks2 < 2; ks2++) {
            unsigned af[4] = {f2h2(e[ks2*2][0],   e[ks2*2][1]),
                              f2h2(e[ks2*2][2],   e[ks2*2][3]),
                              f2h2(e[ks2*2+1][0], e[ks2*2+1][1]),
                              f2h2(e[ks2*2+1][2], e[ks2*2+1][3])};
            #pragma unroll
            for (int nt2 = 0; nt2 < 4; nt2++) {
                unsigned rr[4];
                unsigned a = Vbase
                    + (unsigned)((wn*32 + ks2*16 + (lane & 15))*QPSTR)*4
                    + (unsigned)(nt2*16)*2 + (lane >> 4)*16;
                ldsm4t(rr, a);
                mma16(d[nt2*2    ], af, rr);
                mma16(d[nt2*2 + 1], af, rr + 2);
            }
        }
    }

    // ---- cross-warp key-half reduction + ctx write (red aliases Qs) ----
    __syncthreads();
    if (wn == 1) {
        #pragma unroll
        for (int nt = 0; nt < 8; nt++)
            #pragma unroll
            for (int half = 0; half < 2; half++) {
                int row = wm*16 + g + half*8;
                int col = nt*8 + 2*t;
                *(float2*)(red + row*RSTR + col) =
                    make_float2(d[nt][half*2 + 0], d[nt][half*2 + 1]);
            }
    }
    __syncthreads();
    if (wn == 0) {
        #pragma unroll
        for (int nt = 0; nt < 8; nt++)
            #pragma unroll
            for (int half = 0; half < 2; half++) {
                int row = wm*16 + g + half*8;
                int col = nt*8 + 2*t;
                float2 o = *(const float2*)(red + row*RSTR + col);
                float v0 = d[nt][half*2 + 0] + o.x;
                float v1 = d[nt][half*2 + 1] + o.y;
                *(unsigned*)(g_ch + (size_t)(b*SEQ + q0 + row)*DMODEL + h*DK + col) = f2h2(v0, v1);
            }
    }
}

// ---------------- LayerNorm ----------------
__global__ __launch_bounds__(256) void ln_kernel(
    const float* __restrict__ pre, const float* __restrict__ gamma,
    const float* __restrict__ beta, float* __restrict__ out)
{
    const int tid = threadIdx.x;
    const int row = blockIdx.x;
    float4 v = ((const float4*)(pre + (size_t)row*DMODEL))[tid];
    float s  = v.x + v.y + v.z + v.w;
    float s2 = v.x*v.x + v.y*v.y + v.z*v.z + v.w*v.w;
    #pragma unroll
    for (int o = 16; o > 0; o >>= 1) {
        s  += __shfl_xor_sync(0xffffffffu, s,  o);
        s2 += __shfl_xor_sync(0xffffffffu, s2, o);
    }
    __shared__ float ws[8], ws2[8];
    __shared__ float mu_s, r_s;
    if ((tid & 31) == 0) { ws[tid >> 5] = s; ws2[tid >> 5] = s2; }
    __syncthreads();
    if (tid == 0) {
        float tt = 0.f, t2 = 0.f;
        #pragma unroll
        for (int i = 0; i < 8; i++) { tt += ws[i]; t2 += ws2[i]; }
        float mu  = tt * (1.0f/DMODEL);
        float var = t2 * (1.0f/DMODEL) - mu*mu;
        mu_s = mu;
        r_s  = rsqrtf(var + 1e-5f);
    }
    __syncthreads();
    float mu = mu_s, r = r_s;
    float4 gm = ((const float4*)gamma)[tid];
    float4 be = ((const float4*)beta)[tid];
    float4 o;
    o.x = (v.x - mu)*r*gm.x + be.x;
    o.y = (v.y - mu)*r*gm.y + be.y;
    o.z = (v.z - mu)*r*gm.z + be.z;
    o.w = (v.w - mu)*r*gm.w + be.w;
    ((float4*)(out + (size_t)row*DMODEL))[tid] = o;
}

// ---------------- launch ----------------
extern "C" void kernel_launch(void* const* d_in, const int* in_sizes, int n_in,
                              void* d_out, int out_size)
{
    const float* x     = (const float*)d_in[0];
    const int*   mask  = (const int*)  d_in[1];
    const float* Wq    = (const float*)d_in[2];
    const float* bq    = (const float*)d_in[3];
    const float* Wk    = (const float*)d_in[4];
    const float* bk    = (const float*)d_in[5];
    const float* Wv    = (const float*)d_in[6];
    const float* bv    = (const float*)d_in[7];
    const float* Wo    = (const float*)d_in[8];
    const float* bo    = (const float*)d_in[9];
    const float* gamma = (const float*)d_in[10];
    const float* beta  = (const float*)d_in[11];
    float* out = (float*)d_out;

    void *ppre, *pri;
    cudaGetSymbolAddress(&ppre, g_pre);
    cudaGetSymbolAddress(&pri,  g_rinv);

    const long long OUT_ELEMS = (long long)ROWS * DMODEL;
    float* attout = out + OUT_ELEMS;

    cudaFuncSetAttribute(qkv_tc,     cudaFuncAttributeMaxDynamicSharedMemorySize, GEMM_SMEM);
    cudaFuncSetAttribute(gemmo_tc,   cudaFuncAttributeMaxDynamicSharedMemorySize, GEMM_SMEM);
    cudaFuncSetAttribute(attn_sums,  cudaFuncAttributeMaxDynamicSharedMemorySize, SUM_SMEM);
    cudaFuncSetAttribute(attn_fused, cudaFuncAttributeMaxDynamicSharedMemorySize, FUS_SMEM);

    cvt_kernel<<<dim3(4096, 5), 256>>>(x, Wq, Wk, Wv, Wo);

    qkv_tc<<<dim3(DMODEL/128, ROWS/128, 3), 256, GEMM_SMEM>>>(bq, bk, bv);

    attn_sums<<<dim3(SEQ/128, BH), 256, SUM_SMEM>>>(mask, (float*)pri);
    attn_fused<<<dim3(SEQ/128, BH), 512, FUS_SMEM>>>(mask, (const float*)pri, attout);

    gemmo_tc<<<dim3(DMODEL/128, ROWS/128), 256, GEMM_SMEM>>>(bo, x);
    ln_kernel<<<ROWS, 256>>>((const float*)ppre, gamma, beta, out);
}